// round 13
// baseline (speedup 1.0000x reference)
#include <cuda_runtime.h>
#include <cuda_fp16.h>
#include <cstdint>

// ---------------------------------------------------------------------------
// Problem constants
// ---------------------------------------------------------------------------
#define LAYERS 6
#define SEQ    256
#define BATCH  32
#define NF     1024
#define NH     16
#define HD     64
#define PD     1024
#define FF     4096
#define ROWS   (SEQ*BATCH)     // 8192
#define EPSLN  1e-5f

// ---------------------------------------------------------------------------
// Scratch (device globals; allocation-free per harness rules)
// ---------------------------------------------------------------------------
__device__ float   g_qkv[(size_t)ROWS * 3 * PD];
__device__ __half  g_ah [(size_t)ROWS * NF];
__device__ __half  g_al [(size_t)ROWS * NF];
__device__ __half  g_ffh[(size_t)ROWS * FF];
__device__ __half  g_ffl[(size_t)ROWS * FF];
__device__ __half  g_wh [(size_t)FF * NF];
__device__ __half  g_wl [(size_t)FF * NF];

// ---------------------------------------------------------------------------
// PTX helpers (base sm_103 instruction set ONLY)
// ---------------------------------------------------------------------------
__device__ __forceinline__ uint32_t smem_u32(const void* p) {
    uint32_t a;
    asm("{ .reg .u64 t; cvta.to.shared.u64 t, %1; cvt.u32.u64 %0, t; }"
        : "=r"(a) : "l"(p));
    return a;
}
__device__ __forceinline__ void cp_async16(uint32_t saddr, const void* gaddr) {
    asm volatile("cp.async.cg.shared.global [%0], [%1], 16;"
                 :: "r"(saddr), "l"(gaddr) : "memory");
}
__device__ __forceinline__ void cp_commit() {
    asm volatile("cp.async.commit_group;" ::: "memory");
}
template <int N>
__device__ __forceinline__ void cp_wait() {
    asm volatile("cp.async.wait_group %0;" :: "n"(N) : "memory");
}
__device__ __forceinline__ void ldsm_x4(uint32_t* r, uint32_t addr) {
    asm volatile("ldmatrix.sync.aligned.m8n8.x4.shared.b16 {%0,%1,%2,%3}, [%4];"
                 : "=r"(r[0]), "=r"(r[1]), "=r"(r[2]), "=r"(r[3]) : "r"(addr));
}
__device__ __forceinline__ void ldsm_x2(uint32_t* r, uint32_t addr) {
    asm volatile("ldmatrix.sync.aligned.m8n8.x2.shared.b16 {%0,%1}, [%2];"
                 : "=r"(r[0]), "=r"(r[1]) : "r"(addr));
}
// fp16 inputs, fp32 accumulators (main term)
__device__ __forceinline__ void mma_f32acc(float* c, const uint32_t* a, const uint32_t* b) {
    asm volatile(
        "mma.sync.aligned.m16n8k16.row.col.f32.f16.f16.f32 "
        "{%0,%1,%2,%3}, {%4,%5,%6,%7}, {%8,%9}, {%0,%1,%2,%3};"
        : "+f"(c[0]), "+f"(c[1]), "+f"(c[2]), "+f"(c[3])
        : "r"(a[0]), "r"(a[1]), "r"(a[2]), "r"(a[3]), "r"(b[0]), "r"(b[1]));
}
// fp16 inputs, fp16 accumulators (correction terms)
__device__ __forceinline__ void mma_f16acc(uint32_t* c, const uint32_t* a, const uint32_t* b) {
    asm volatile(
        "mma.sync.aligned.m16n8k16.row.col.f16.f16.f16.f16 "
        "{%0,%1}, {%2,%3,%4,%5}, {%6,%7}, {%0,%1};"
        : "+r"(c[0]), "+r"(c[1])
        : "r"(a[0]), "r"(a[1]), "r"(a[2]), "r"(a[3]), "r"(b[0]), "r"(b[1]));
}

// f32x2 helpers for attention
__device__ __forceinline__ unsigned long long fma2(unsigned long long a,
                                                   unsigned long long b,
                                                   unsigned long long c) {
    unsigned long long d;
    asm("fma.rn.f32x2 %0, %1, %2, %3;" : "=l"(d) : "l"(a), "l"(b), "l"(c));
    return d;
}
__device__ __forceinline__ void unpack2(unsigned long long v, float& lo, float& hi) {
    asm("mov.b64 {%0, %1}, %2;" : "=f"(lo), "=f"(hi) : "l"(v));
}

// ---------------------------------------------------------------------------
// Utility kernels
// ---------------------------------------------------------------------------
__global__ __launch_bounds__(256) void copy_kernel(const float* __restrict__ src,
                                                   float* __restrict__ dst) {
    size_t i = (size_t)blockIdx.x * 256 + threadIdx.x;
    ((float4*)dst)[i] = ((const float4*)src)[i];
}

// fp32 -> fp16 hi/lo split (weights)
__global__ __launch_bounds__(256) void convw_kernel(const float* __restrict__ w,
                                                    __half* __restrict__ hi,
                                                    __half* __restrict__ lo) {
    size_t i = (size_t)blockIdx.x * 256 + threadIdx.x;
    float4 v = ((const float4*)w)[i];
    __half hx = __float2half_rn(v.x);
    __half hy = __float2half_rn(v.y);
    __half hz = __float2half_rn(v.z);
    __half hw = __float2half_rn(v.w);
    __half2 h0 = __halves2half2(hx, hy);
    __half2 h1 = __halves2half2(hz, hw);
    __half2 l0 = __halves2half2(__float2half_rn(v.x - __half2float(hx)),
                                __float2half_rn(v.y - __half2float(hy)));
    __half2 l1 = __halves2half2(__float2half_rn(v.z - __half2float(hz)),
                                __float2half_rn(v.w - __half2float(hw)));
    ((__half2*)hi)[2 * i]     = h0;
    ((__half2*)hi)[2 * i + 1] = h1;
    ((__half2*)lo)[2 * i]     = l0;
    ((__half2*)lo)[2 * i + 1] = l1;
}

// ---------------------------------------------------------------------------
// LayerNorm over N=1024. MODE 0: fp32 out. MODE 1: fp16 hi/lo out.
// ---------------------------------------------------------------------------
template <int MODE>
__global__ __launch_bounds__(256) void ln_kernel(const float* __restrict__ x,
                                                 const float* __restrict__ g,
                                                 const float* __restrict__ b,
                                                 float* __restrict__ y,
                                                 __half* __restrict__ oh,
                                                 __half* __restrict__ ol) {
    int row = blockIdx.x;
    int t   = threadIdx.x;
    const float4* xr = (const float4*)(x + (size_t)row * NF);
    float4 v = xr[t];

    __shared__ float red[8];
    float s = v.x + v.y + v.z + v.w;
    #pragma unroll
    for (int o = 16; o; o >>= 1) s += __shfl_xor_sync(0xffffffffu, s, o);
    if ((t & 31) == 0) red[t >> 5] = s;
    __syncthreads();
    float tot = red[0] + red[1] + red[2] + red[3] + red[4] + red[5] + red[6] + red[7];
    float mean = tot * (1.0f / NF);
    __syncthreads();

    float dx = v.x - mean, dy = v.y - mean, dz = v.z - mean, dw = v.w - mean;
    float sq = dx * dx + dy * dy + dz * dz + dw * dw;
    #pragma unroll
    for (int o = 16; o; o >>= 1) sq += __shfl_xor_sync(0xffffffffu, sq, o);
    if ((t & 31) == 0) red[t >> 5] = sq;
    __syncthreads();
    float vtot = red[0] + red[1] + red[2] + red[3] + red[4] + red[5] + red[6] + red[7];
    float inv = rsqrtf(vtot * (1.0f / NF) + EPSLN);

    float4 gg = ((const float4*)g)[t];
    float4 bb = ((const float4*)b)[t];
    float4 out;
    out.x = dx * inv * gg.x + bb.x;
    out.y = dy * inv * gg.y + bb.y;
    out.z = dz * inv * gg.z + bb.z;
    out.w = dw * inv * gg.w + bb.w;

    if (MODE == 0) {
        ((float4*)(y + (size_t)row * NF))[t] = out;
    } else {
        size_t base = (size_t)row * NF + (size_t)t * 4;
        __half hx = __float2half_rn(out.x);
        __half hy = __float2half_rn(out.y);
        __half hz = __float2half_rn(out.z);
        __half hw = __float2half_rn(out.w);
        __half2 h0 = __halves2half2(hx, hy);
        __half2 h1 = __halves2half2(hz, hw);
        __half2 l0 = __halves2half2(__float2half_rn(out.x - __half2float(hx)),
                                    __float2half_rn(out.y - __half2float(hy)));
        __half2 l1 = __halves2half2(__float2half_rn(out.z - __half2float(hz)),
                                    __float2half_rn(out.w - __half2float(hw)));
        *(__half2*)(oh + base)     = h0;
        *(__half2*)(oh + base + 2) = h1;
        *(__half2*)(ol + base)     = l0;
        *(__half2*)(ol + base + 2) = l1;
    }
}

// ---------------------------------------------------------------------------
// HMMA GEMM: C[M,Nn] = (Ah+Al)[M,K] @ (Wh+Wl)[Nn,K]^T (+bias)(+epilogue)
// fp16 hi/lo split: main AhWh fp32 acc; corrections AhWl + AlWh fp16 acc.
// CTA tile 128x128, 8 warps (2x4), warp tile 64x32, K-chunk 64,
// 3-stage cp.async ring + FRAGMENT DOUBLE BUFFERING across ks-steps
// (prefetch ks+1 fragments during ks mma work to kill correlated LDS stalls).
// EPI 0: bias, fp32 store. EPI 1: bias+relu -> fp16 hi/lo. EPI 2: C += acc+bias.
// ---------------------------------------------------------------------------
#define KC   64
#define AST  72                       // padded row length (fp16 elems)
#define ARB  (AST*2)                  // 144 bytes/row
#define TILEB (128*ARB)               // 18432 B per array tile
#define STAGEB (4*TILEB)              // 73728 B per stage (Ah|Al|Wh|Wl)
#define NSTAGE 3
#define GEMM_SMEM (NSTAGE*STAGEB)     // 221184 B

__device__ __forceinline__ void gemm_issue_chunk(
    const __half* pAh, const __half* pAl,
    const __half* pWh, const __half* pWl,
    int K, int c, uint32_t dst0, int tid) {
    const __half* srcs[4] = {pAh + (size_t)c * KC, pAl + (size_t)c * KC,
                             pWh + (size_t)c * KC, pWl + (size_t)c * KC};
    #pragma unroll
    for (int arr = 0; arr < 4; arr++) {
        const __half* p = srcs[arr];
        uint32_t d0 = dst0 + arr * TILEB;
        #pragma unroll
        for (int i = 0; i < 4; i++) {
            int idx = i * 256 + tid;
            int r = idx >> 3, cc = idx & 7;
            cp_async16(d0 + r * ARB + cc * 16, p + (size_t)r * K + cc * 8);
        }
    }
    cp_commit();
}

// load one ks-step's fragments into a buffer
__device__ __forceinline__ void load_frags(
    uint32_t (&ah)[4][4], uint32_t (&al)[4][4],
    uint32_t (&wh)[4][2], uint32_t (&wl)[4][2],
    uint32_t sA, uint32_t sAl, uint32_t sW, uint32_t sWl,
    int arow, int acolb, int brow, int bcolb, int ks) {
    #pragma unroll
    for (int i = 0; i < 4; i++) {
        uint32_t off = (uint32_t)(arow + i * 16) * ARB + ks * 32 + acolb;
        ldsm_x4(ah[i], sA + off);
        ldsm_x4(al[i], sAl + off);
    }
    #pragma unroll
    for (int j = 0; j < 4; j++) {
        uint32_t off = (uint32_t)(brow + j * 8) * ARB + ks * 32 + bcolb;
        ldsm_x2(wh[j], sW + off);
        ldsm_x2(wl[j], sWl + off);
    }
}

template <int EPI>
__global__ __launch_bounds__(256, 1)
void tc_gemm(const __half* __restrict__ Ah, const __half* __restrict__ Al,
             const __half* __restrict__ Wh, const __half* __restrict__ Wl,
             const float* __restrict__ bias, float* __restrict__ C,
             __half* __restrict__ Oh, __half* __restrict__ Ol,
             int Nn, int K) {
    extern __shared__ __align__(16) char smem[];
    __shared__ float sbias[128];
    uint32_t sb = smem_u32(smem);
    int tid = threadIdx.x;
    int bm = blockIdx.y * 128;
    int bn = blockIdx.x * 128;

    if (tid < 128) sbias[tid] = bias[bn + tid];

    const __half* pAh = Ah + (size_t)bm * K;
    const __half* pAl = Al + (size_t)bm * K;
    const __half* pWh = Wh + (size_t)bn * K;
    const __half* pWl = Wl + (size_t)bn * K;

    int l = tid & 31, warp = tid >> 5;
    int wm = warp >> 2, wn = warp & 3;       // 2x4 warps, warp tile 64x32

    float acc[4][4][4];                       // main term, fp32 acc
    uint32_t cor[4][4][2];                    // corrections, fp16 acc
    #pragma unroll
    for (int i = 0; i < 4; i++)
        #pragma unroll
        for (int j = 0; j < 4; j++) {
            #pragma unroll
            for (int k = 0; k < 4; k++) acc[i][j][k] = 0.0f;
            cor[i][j][0] = 0u; cor[i][j][1] = 0u;
        }

    // ldmatrix lane addressing (R9-validated mapping)
    int arow  = wm * 64 + (l & 15);
    int acolb = (l >> 4) * 16;
    int brow  = wn * 32 + (l & 7);
    int bcolb = ((l >> 3) & 1) * 16;

    int NC = K / KC;

    gemm_issue_chunk(pAh, pAl, pWh, pWl, K, 0, sb, tid);
    gemm_issue_chunk(pAh, pAl, pWh, pWl, K, 1, sb + STAGEB, tid);

    // double-buffered fragments
    uint32_t fah[2][4][4], fal[2][4][4], fwh[2][4][2], fwl[2][4][2];

    int stage = 0;
    for (int c = 0; c < NC; c++) {
        if (c + 1 < NC) cp_wait<1>(); else cp_wait<0>();
        __syncthreads();

        uint32_t sA  = sb + stage * STAGEB;
        uint32_t sAl = sA + TILEB;
        uint32_t sW  = sA + 2 * TILEB;
        uint32_t sWl = sA + 3 * TILEB;

        // prime fragment pipeline with ks=0
        load_frags(fah[0], fal[0], fwh[0], fwl[0],
                   sA, sAl, sW, sWl, arow, acolb, brow, bcolb, 0);

        // refill the stage drained by the barrier (held chunk c-1) with c+2
        if (c + 2 < NC) {
            int ns = stage + 2; if (ns >= NSTAGE) ns -= NSTAGE;
            gemm_issue_chunk(pAh, pAl, pWh, pWl, K, c + 2, sb + ns * STAGEB, tid);
        }

        #pragma unroll
        for (int ks = 0; ks < KC / 16; ks++) {
            int cur = ks & 1;
            if (ks + 1 < KC / 16)
                load_frags(fah[cur ^ 1], fal[cur ^ 1], fwh[cur ^ 1], fwl[cur ^ 1],
                           sA, sAl, sW, sWl, arow, acolb, brow, bcolb, ks + 1);
            #pragma unroll
            for (int i = 0; i < 4; i++)
                #pragma unroll
                for (int j = 0; j < 4; j++) {
                    mma_f32acc(acc[i][j], fah[cur][i], fwh[cur][j]);  // main
                    mma_f16acc(cor[i][j], fah[cur][i], fwl[cur][j]);  // corr
                    mma_f16acc(cor[i][j], fal[cur][i], fwh[cur][j]);  // corr
                }
        }
        if (++stage >= NSTAGE) stage = 0;
    }

    // epilogue: main fragment (c0,c1)->(row,col..col+1); (c2,c3)->(row+8,..)
    // correction reg 'half' = half2(c_{2half}, c_{2half+1}) with same mapping.
    int r0 = bm + wm * 64 + (l >> 2);
    int cb = wn * 32 + 2 * (l & 3);
    #pragma unroll
    for (int i = 0; i < 4; i++) {
        #pragma unroll
        for (int j = 0; j < 4; j++) {
            int col = cb + j * 8;
            float b0 = sbias[col], b1 = sbias[col + 1];
            #pragma unroll
            for (int half = 0; half < 2; half++) {
                __half2 ch = *(__half2*)&cor[i][j][half];
                float2 cf = __half22float2(ch);
                int m = r0 + i * 16 + half * 8;
                float v0 = acc[i][j][2 * half]     + cf.x + b0;
                float v1 = acc[i][j][2 * half + 1] + cf.y + b1;
                size_t idx = (size_t)m * Nn + bn + col;
                if (EPI == 0) {
                    float2 s = {v0, v1};
                    *(float2*)(C + idx) = s;
                } else if (EPI == 2) {
                    float2 old = *(const float2*)(C + idx);
                    float2 s = {v0 + old.x, v1 + old.y};
                    *(float2*)(C + idx) = s;
                } else {  // EPI 1: relu -> fp16 hi/lo split
                    v0 = fmaxf(v0, 0.0f);
                    v1 = fmaxf(v1, 0.0f);
                    __half h0 = __float2half_rn(v0);
                    __half h1 = __float2half_rn(v1);
                    __half2 h2 = __halves2half2(h0, h1);
                    __half2 l2 = __halves2half2(
                        __float2half_rn(v0 - __half2float(h0)),
                        __float2half_rn(v1 - __half2float(h1)));
                    *(__half2*)(Oh + idx) = h2;
                    *(__half2*)(Ol + idx) = l2;
                }
            }
        }
    }
}

// ---------------------------------------------------------------------------
// Fused attention: one CTA per (b,h), 512 threads, K/V resident in SMEM.
// Reads qkv fp32, writes attention output as fp16 hi/lo split.
// ---------------------------------------------------------------------------
#define KST 68
#define ATTN_SMEM ((SEQ*KST + SEQ*HD + 16*4*SEQ) * 4)

__global__ __launch_bounds__(512, 1) void attn_kernel(const float* __restrict__ qkv,
                                                      const float* __restrict__ mask,
                                                      __half* __restrict__ oh,
                                                      __half* __restrict__ ol) {
    extern __shared__ __align__(16) float sm[];
    float* Ks = sm;
    float* Vs = Ks + SEQ * KST;
    float* Ps = Vs + SEQ * HD;

    int bh = blockIdx.x;
    int b  = bh >> 4;
    int h  = bh & 15;
    int tid = threadIdx.x;

    for (int idx = tid; idx < SEQ * 16; idx += 512) {
        int s = idx >> 4;
        int c = (idx & 15) << 2;
        size_t base = ((size_t)s * BATCH + b) * (3 * PD) + (size_t)h * HD + c;
        float4 k4 = *(const float4*)(qkv + base + PD);
        float4 v4 = *(const float4*)(qkv + base + 2 * PD);
        *(float4*)(Ks + s * KST + c) = k4;
        *(float4*)(Vs + s * HD + c) = v4;
    }
    __syncthreads();

    int warp = tid >> 5, lane = tid & 31;
    float* Pw = Ps + warp * 4 * SEQ;
    const size_t qtstep = (size_t)BATCH * 3 * PD;

    for (int it = 0; it < 4; it++) {
        int t0 = warp * 16 + it * 4;
        const float* qp0 = qkv + ((size_t)t0 * BATCH + b) * (3 * PD) + (size_t)h * HD;

        unsigned long long sc2[4][8];
        #pragma unroll
        for (int q = 0; q < 4; q++)
            #pragma unroll
            for (int j = 0; j < 8; j++) sc2[q][j] = 0ull;

        #pragma unroll 2
        for (int d4 = 0; d4 < 16; d4++) {
            const float* qb = qp0 + 4 * d4;
            ulonglong2 aq0 = *(const ulonglong2*)(qb);
            ulonglong2 aq1 = *(const ulonglong2*)(qb + qtstep);
            ulonglong2 aq2 = *(const ulonglong2*)(qb + 2 * qtstep);
            ulonglong2 aq3 = *(const ulonglong2*)(qb + 3 * qtstep);
            #pragma unroll
            for (int j = 0; j < 8; j++) {
                int s = lane + 32 * j;
                ulonglong2 k2 = *(const ulonglong2*)(Ks + s * KST + 4 * d4);
                sc2[0][j] = fma2(aq0.x, k2.x, sc2[0][j]);
                sc2[0][j] = fma2(aq0.y, k2.y, sc2[0][j]);
                sc2[1][j] = fma2(aq1.x, k2.x, sc2[1][j]);
                sc2[1][j] = fma2(aq1.y, k2.y, sc2[1][j]);
                sc2[2][j] = fma2(aq2.x, k2.x, sc2[2][j]);
                sc2[2][j] = fma2(aq2.y, k2.y, sc2[2][j]);
                sc2[3][j] = fma2(aq3.x, k2.x, sc2[3][j]);
                sc2[3][j] = fma2(aq3.y, k2.y, sc2[3][j]);
            }
        }

        #pragma unroll
        for (int q = 0; q < 4; q++) {
            float pr[8];
            const float* mrow = mask + (size_t)(t0 + q) * SEQ;
            #pragma unroll
            for (int j = 0; j < 8; j++) {
                float lo, hi;
                unpack2(sc2[q][j], lo, hi);
                pr[j] = (lo + hi) * 0.125f + mrow[lane + 32 * j];
            }
            float mx = pr[0];
            #pragma unroll
            for (int j = 1; j < 8; j++) mx = fmaxf(mx, pr[j]);
            #pragma unroll
            for (int o = 16; o; o >>= 1) mx = fmaxf(mx, __shfl_xor_sync(0xffffffffu, mx, o));
            float sum = 0.0f;
            #pragma unroll
            for (int j = 0; j < 8; j++) { pr[j] = __expf(pr[j] - mx); sum += pr[j]; }
            #pragma unroll
            for (int o = 16; o; o >>= 1) sum += __shfl_xor_sync(0xffffffffu, sum, o);
            float inv = 1.0f / sum;
            #pragma unroll
            for (int j = 0; j < 8; j++) Pw[q * SEQ + lane + 32 * j] = pr[j] * inv;
        }
        __syncwarp();

        float2 acc0 = {0, 0}, acc1 = {0, 0}, acc2v = {0, 0}, acc3 = {0, 0};
        const float* vcol = Vs + 2 * lane;
        for (int s = 0; s < SEQ; s++) {
            float2 v2 = *(const float2*)(vcol + s * HD);
            float p0 = Pw[s];
            float p1 = Pw[SEQ + s];
            float p2 = Pw[2 * SEQ + s];
            float p3 = Pw[3 * SEQ + s];
            acc0.x = fmaf(p0, v2.x, acc0.x); acc0.y = fmaf(p0, v2.y, acc0.y);
            acc1.x = fmaf(p1, v2.x, acc1.x); acc1.y = fmaf(p1, v2.y, acc1.y);
            acc2v.x = fmaf(p2, v2.x, acc2v.x); acc2v.y = fmaf(p2, v2.y, acc2v.y);
            acc3.x = fmaf(p3, v2.x, acc3.x); acc3.y = fmaf(p3, v2.y, acc3.y);
        }
        size_t obase = ((size_t)t0 * BATCH + b) * PD + (size_t)h * HD + 2 * lane;
        size_t ostep = (size_t)BATCH * PD;
        float2 accs[4] = {acc0, acc1, acc2v, acc3};
        #pragma unroll
        for (int q = 0; q < 4; q++) {
            size_t oidx = obase + q * ostep;
            __half hx = __float2half_rn(accs[q].x);
            __half hy = __float2half_rn(accs[q].y);
            __half2 h2 = __halves2half2(hx, hy);
            __half2 l2 = __halves2half2(
                __float2half_rn(accs[q].x - __half2float(hx)),
                __float2half_rn(accs[q].y - __half2float(hy)));
            *(__half2*)(oh + oidx) = h2;
            *(__half2*)(ol + oidx) = l2;
        }
        __syncwarp();
    }
}

// ---------------------------------------------------------------------------
// Host orchestration
// ---------------------------------------------------------------------------
extern "C" void kernel_launch(void* const* d_in, const int* in_sizes, int n_in,
                              void* d_out, int out_size) {
    const float* src  = (const float*)d_in[0];
    const float* mask = (const float*)d_in[1];
    const float* Wqkv = (const float*)d_in[2];
    const float* bqkv = (const float*)d_in[3];
    const float* Wo   = (const float*)d_in[4];
    const float* bo   = (const float*)d_in[5];
    const float* ln1g = (const float*)d_in[6];
    const float* ln1b = (const float*)d_in[7];
    const float* ln2g = (const float*)d_in[8];
    const float* ln2b = (const float*)d_in[9];
    const float* W1   = (const float*)d_in[10];
    const float* b1   = (const float*)d_in[11];
    const float* W2   = (const float*)d_in[12];
    const float* b2   = (const float*)d_in[13];
    const float* lnfg = (const float*)d_in[14];
    const float* lnfb = (const float*)d_in[15];

    float* x = (float*)d_out;

    void *pqkv, *pah, *pal, *pffh, *pffl, *pwh, *pwl;
    cudaGetSymbolAddress(&pqkv, g_qkv);
    cudaGetSymbolAddress(&pah, g_ah);
    cudaGetSymbolAddress(&pal, g_al);
    cudaGetSymbolAddress(&pffh, g_ffh);
    cudaGetSymbolAddress(&pffl, g_ffl);
    cudaGetSymbolAddress(&pwh, g_wh);
    cudaGetSymbolAddress(&pwl, g_wl);
    float* qk = (float*)pqkv;
    __half* ah  = (__half*)pah;
    __half* al  = (__half*)pal;
    __half* ffh = (__half*)pffh;
    __half* ffl = (__half*)pffl;
    __half* wh  = (__half*)pwh;
    __half* wl  = (__half*)pwl;

    cudaFuncSetAttribute(attn_kernel, cudaFuncAttributeMaxDynamicSharedMemorySize,
                         ATTN_SMEM);
    cudaFuncSetAttribute(tc_gemm<0>, cudaFuncAttributeMaxDynamicSharedMemorySize,
                         GEMM_SMEM);
    cudaFuncSetAttribute(tc_gemm<1>, cudaFuncAttributeMaxDynamicSharedMemorySize,
                         GEMM_SMEM);
    cudaFuncSetAttribute(tc_gemm<2>, cudaFuncAttributeMaxDynamicSharedMemorySize,
                         GEMM_SMEM);

    // x = src
    copy_kernel<<<ROWS * NF / (256 * 4), 256>>>(src, x);

    dim3 gQKV(3 * PD / 128, ROWS / 128);   // (24, 64)
    dim3 gWO(NF / 128, ROWS / 128);        // (8, 64)
    dim3 gW1(FF / 128, ROWS / 128);        // (32, 64)
    dim3 gW2(NF / 128, ROWS / 128);        // (8, 64)

    for (int l = 0; l < LAYERS; l++) {
        const float* wqkv = Wqkv + (size_t)l * 3 * PD * NF;
        const float* bq   = bqkv + (size_t)l * 3 * PD;
        const float* wo   = Wo   + (size_t)l * NF * PD;
        const float* bo_  = bo   + (size_t)l * NF;
        const float* w1   = W1   + (size_t)l * FF * NF;
        const float* bb1  = b1   + (size_t)l * FF;
        const float* w2   = W2   + (size_t)l * NF * FF;
        const float* bb2  = b2   + (size_t)l * NF;

        // --- attention block ---
        ln_kernel<1><<<ROWS, 256>>>(x, ln1g + (size_t)l * NF, ln1b + (size_t)l * NF,
                                    nullptr, ah, al);
        convw_kernel<<<(3 * PD * NF) / 1024, 256>>>(wqkv, wh, wl);
        tc_gemm<0><<<gQKV, 256, GEMM_SMEM>>>(ah, al, wh, wl, bq, qk,
                                             nullptr, nullptr, 3 * PD, NF);
        attn_kernel<<<BATCH * NH, 512, ATTN_SMEM>>>(qk, mask, ah, al);
        convw_kernel<<<(NF * PD) / 1024, 256>>>(wo, wh, wl);
        tc_gemm<2><<<gWO, 256, GEMM_SMEM>>>(ah, al, wh, wl, bo_, x,
                                            nullptr, nullptr, NF, PD);

        // --- FFN block ---
        ln_kernel<1><<<ROWS, 256>>>(x, ln2g + (size_t)l * NF, ln2b + (size_t)l * NF,
                                    nullptr, ah, al);
        convw_kernel<<<(FF * NF) / 1024, 256>>>(w1, wh, wl);
        tc_gemm<1><<<gW1, 256, GEMM_SMEM>>>(ah, al, wh, wl, bb1, nullptr,
                                            ffh, ffl, FF, NF);
        convw_kernel<<<(NF * FF) / 1024, 256>>>(w2, wh, wl);
        tc_gemm<2><<<gW2, 256, GEMM_SMEM>>>(ffh, ffl, wh, wl, bb2, x,
                                            nullptr, nullptr, NF, FF);
    }

    // final LN (fp32, in-place on d_out)
    ln_kernel<0><<<ROWS, 256>>>(x, lnfg, lnfb, x, nullptr, nullptr);
}

// round 15
// speedup vs baseline: 1.8036x; 1.8036x over previous
#include <cuda_runtime.h>
#include <cuda_fp16.h>
#include <cstdint>

// ---------------------------------------------------------------------------
// Arch-specific feature gate: tcgen05 compiles ONLY in sm_103a/103f passes.
// The plain sm_103 ptxas pass sees the HMMA fallback (R12-exact).
// ---------------------------------------------------------------------------
#if (defined(__CUDA_ARCH_SPECIFIC__) && (__CUDA_ARCH_SPECIFIC__ == 1030)) || \
    (defined(__CUDA_ARCH_FAMILY_SPECIFIC__) && (__CUDA_ARCH_FAMILY_SPECIFIC__ == 1030)) || \
    defined(__CUDA_ARCH_FEAT_SM103_ALL)
#define USE_TCGEN05 1
#else
#define USE_TCGEN05 0
#endif

// ---------------------------------------------------------------------------
// Problem constants
// ---------------------------------------------------------------------------
#define LAYERS 6
#define SEQ    256
#define BATCH  32
#define NF     1024
#define NH     16
#define HD     64
#define PD     1024
#define FF     4096
#define ROWS   (SEQ*BATCH)     // 8192
#define EPSLN  1e-5f

// ---------------------------------------------------------------------------
// Scratch (device globals; allocation-free per harness rules)
// ---------------------------------------------------------------------------
__device__ float   g_qkv[(size_t)ROWS * 3 * PD];
__device__ __half  g_ah [(size_t)ROWS * NF];
__device__ __half  g_al [(size_t)ROWS * NF];
__device__ __half  g_ffh[(size_t)ROWS * FF];
__device__ __half  g_ffl[(size_t)ROWS * FF];
__device__ __half  g_wh [(size_t)FF * NF];
__device__ __half  g_wl [(size_t)FF * NF];

// ---------------------------------------------------------------------------
// PTX helpers (base sm_103 instruction set)
// ---------------------------------------------------------------------------
__device__ __forceinline__ uint32_t smem_u32(const void* p) {
    uint32_t a;
    asm("{ .reg .u64 t; cvta.to.shared.u64 t, %1; cvt.u32.u64 %0, t; }"
        : "=r"(a) : "l"(p));
    return a;
}
__device__ __forceinline__ void cp_async16(uint32_t saddr, const void* gaddr) {
    asm volatile("cp.async.cg.shared.global [%0], [%1], 16;"
                 :: "r"(saddr), "l"(gaddr) : "memory");
}
__device__ __forceinline__ void cp_commit() {
    asm volatile("cp.async.commit_group;" ::: "memory");
}
template <int N>
__device__ __forceinline__ void cp_wait() {
    asm volatile("cp.async.wait_group %0;" :: "n"(N) : "memory");
}
__device__ __forceinline__ void ldsm_x4(uint32_t* r, uint32_t addr) {
    asm volatile("ldmatrix.sync.aligned.m8n8.x4.shared.b16 {%0,%1,%2,%3}, [%4];"
                 : "=r"(r[0]), "=r"(r[1]), "=r"(r[2]), "=r"(r[3]) : "r"(addr));
}
__device__ __forceinline__ void mma_f32acc(float* c, const uint32_t* a, const uint32_t* b) {
    asm volatile(
        "mma.sync.aligned.m16n8k16.row.col.f32.f16.f16.f32 "
        "{%0,%1,%2,%3}, {%4,%5,%6,%7}, {%8,%9}, {%0,%1,%2,%3};"
        : "+f"(c[0]), "+f"(c[1]), "+f"(c[2]), "+f"(c[3])
        : "r"(a[0]), "r"(a[1]), "r"(a[2]), "r"(a[3]), "r"(b[0]), "r"(b[1]));
}
__device__ __forceinline__ void mma_f16acc(uint32_t* c, const uint32_t* a, const uint32_t* b) {
    asm volatile(
        "mma.sync.aligned.m16n8k16.row.col.f16.f16.f16.f16 "
        "{%0,%1}, {%2,%3,%4,%5}, {%6,%7}, {%0,%1};"
        : "+r"(c[0]), "+r"(c[1])
        : "r"(a[0]), "r"(a[1]), "r"(a[2]), "r"(a[3]), "r"(b[0]), "r"(b[1]));
}

// f32x2 helpers for attention
__device__ __forceinline__ unsigned long long fma2(unsigned long long a,
                                                   unsigned long long b,
                                                   unsigned long long c) {
    unsigned long long d;
    asm("fma.rn.f32x2 %0, %1, %2, %3;" : "=l"(d) : "l"(a), "l"(b), "l"(c));
    return d;
}
__device__ __forceinline__ void unpack2(unsigned long long v, float& lo, float& hi) {
    asm("mov.b64 {%0, %1}, %2;" : "=f"(lo), "=f"(hi) : "l"(v));
}

#if USE_TCGEN05
// ---------------------------------------------------------------------------
// tcgen05 helpers (compiled only in sm_103a/103f passes)
// ---------------------------------------------------------------------------
__device__ __forceinline__ bool elect_one() {
    uint32_t p;
    asm volatile("{\n\t.reg .pred P;\n\telect.sync _|P, 0xFFFFFFFF;\n\t"
                 "selp.b32 %0, 1, 0, P;\n\t}" : "=r"(p));
    return p != 0;
}
__device__ __forceinline__ void t_mbar_init(uint32_t mbar, uint32_t cnt) {
    asm volatile("mbarrier.init.shared.b64 [%0], %1;" :: "r"(mbar), "r"(cnt) : "memory");
}
__device__ __forceinline__ void t_mbar_inval(uint32_t mbar) {
    asm volatile("mbarrier.inval.shared.b64 [%0];" :: "r"(mbar) : "memory");
}
__device__ __forceinline__ void t_mbar_wait(uint32_t mbar, uint32_t phase) {
    asm volatile(
        "{\n\t.reg .pred P;\n\t"
        "WL_%=:\n\t"
        "mbarrier.try_wait.parity.acquire.cta.shared::cta.b64 P, [%0], %1, 0x989680;\n\t"
        "@P bra.uni WD_%=;\n\t"
        "bra.uni WL_%=;\n\t"
        "WD_%=:\n\t}"
        :: "r"(mbar), "r"(phase) : "memory");
}
__device__ __forceinline__ void t_alloc(uint32_t smem_dst, uint32_t ncols) {
    asm volatile("tcgen05.alloc.cta_group::1.sync.aligned.shared::cta.b32 [%0], %1;"
                 :: "r"(smem_dst), "r"(ncols) : "memory");
}
__device__ __forceinline__ void t_dealloc(uint32_t tmem, uint32_t ncols) {
    asm volatile("tcgen05.dealloc.cta_group::1.sync.aligned.b32 %0, %1;"
                 :: "r"(tmem), "r"(ncols));
}
__device__ __forceinline__ void t_mma_f16_ss(uint32_t d, unsigned long long a,
                                             unsigned long long b, uint32_t idesc,
                                             uint32_t en) {
    asm volatile(
        "{\n\t.reg .pred p;\n\t"
        "setp.ne.u32 p, %4, 0;\n\t"
        "tcgen05.mma.cta_group::1.kind::f16 [%0], %1, %2, %3, {%5, %5, %5, %5}, p;\n\t}"
        :: "r"(d), "l"(a), "l"(b), "r"(idesc), "r"(en), "r"(0u)
        : "memory");
}
__device__ __forceinline__ void t_commit(uint32_t mbar) {
    asm volatile(
        "tcgen05.commit.cta_group::1.mbarrier::arrive::one.shared::cluster.b64 [%0];"
        :: "r"(mbar) : "memory");
}
__device__ __forceinline__ void t_ld_x32(uint32_t* r, uint32_t addr) {
    asm volatile(
        "tcgen05.ld.sync.aligned.32x32b.x32.b32 "
        "{%0, %1, %2, %3, %4, %5, %6, %7, "
        " %8, %9, %10, %11, %12, %13, %14, %15, "
        " %16, %17, %18, %19, %20, %21, %22, %23, "
        " %24, %25, %26, %27, %28, %29, %30, %31}, [%32];"
        : "=r"(r[0]),  "=r"(r[1]),  "=r"(r[2]),  "=r"(r[3]),
          "=r"(r[4]),  "=r"(r[5]),  "=r"(r[6]),  "=r"(r[7]),
          "=r"(r[8]),  "=r"(r[9]),  "=r"(r[10]), "=r"(r[11]),
          "=r"(r[12]), "=r"(r[13]), "=r"(r[14]), "=r"(r[15]),
          "=r"(r[16]), "=r"(r[17]), "=r"(r[18]), "=r"(r[19]),
          "=r"(r[20]), "=r"(r[21]), "=r"(r[22]), "=r"(r[23]),
          "=r"(r[24]), "=r"(r[25]), "=r"(r[26]), "=r"(r[27]),
          "=r"(r[28]), "=r"(r[29]), "=r"(r[30]), "=r"(r[31])
        : "r"(addr));
}
__device__ __forceinline__ void t_wait_ld() {
    asm volatile("tcgen05.wait::ld.sync.aligned;" ::: "memory");
}
__device__ __forceinline__ void t_fence_after() {
    asm volatile("tcgen05.fence::after_thread_sync;" ::: "memory");
}
__device__ __forceinline__ void t_fence_before() {
    asm volatile("tcgen05.fence::before_thread_sync;" ::: "memory");
}
__device__ __forceinline__ void fence_async_smem() {
    asm volatile("fence.proxy.async.shared::cta;" ::: "memory");
}
// SW128 smem descriptor: layout=SW128, version=1, SBO=64, LBO=1
#define DESC_BASE_SW128 0x4000404000010000ULL
__device__ __forceinline__ unsigned long long mkdesc(uint32_t smem_addr) {
    return DESC_BASE_SW128 | (unsigned long long)((smem_addr >> 4) & 0x3FFF);
}
// idesc kind::f16: f32 acc (1<<4), atype=btype=f16 (0), N=128 (16<<17), M=128 (8<<24)
#define TC_IDESC 0x08200010u
#endif // USE_TCGEN05

// ---------------------------------------------------------------------------
// Utility kernels
// ---------------------------------------------------------------------------
__global__ __launch_bounds__(256) void copy_kernel(const float* __restrict__ src,
                                                   float* __restrict__ dst) {
    size_t i = (size_t)blockIdx.x * 256 + threadIdx.x;
    ((float4*)dst)[i] = ((const float4*)src)[i];
}

// fp32 -> fp16 hi/lo split (weights)
__global__ __launch_bounds__(256) void convw_kernel(const float* __restrict__ w,
                                                    __half* __restrict__ hi,
                                                    __half* __restrict__ lo) {
    size_t i = (size_t)blockIdx.x * 256 + threadIdx.x;
    float4 v = ((const float4*)w)[i];
    __half hx = __float2half_rn(v.x);
    __half hy = __float2half_rn(v.y);
    __half hz = __float2half_rn(v.z);
    __half hw = __float2half_rn(v.w);
    __half2 h0 = __halves2half2(hx, hy);
    __half2 h1 = __halves2half2(hz, hw);
    __half2 l0 = __halves2half2(__float2half_rn(v.x - __half2float(hx)),
                                __float2half_rn(v.y - __half2float(hy)));
    __half2 l1 = __halves2half2(__float2half_rn(v.z - __half2float(hz)),
                                __float2half_rn(v.w - __half2float(hw)));
    ((__half2*)hi)[2 * i]     = h0;
    ((__half2*)hi)[2 * i + 1] = h1;
    ((__half2*)lo)[2 * i]     = l0;
    ((__half2*)lo)[2 * i + 1] = l1;
}

// ---------------------------------------------------------------------------
// LayerNorm over N=1024. MODE 0: fp32 out. MODE 1: fp16 hi/lo out.
// ---------------------------------------------------------------------------
template <int MODE>
__global__ __launch_bounds__(256) void ln_kernel(const float* __restrict__ x,
                                                 const float* __restrict__ g,
                                                 const float* __restrict__ b,
                                                 float* __restrict__ y,
                                                 __half* __restrict__ oh,
                                                 __half* __restrict__ ol) {
    int row = blockIdx.x;
    int t   = threadIdx.x;
    const float4* xr = (const float4*)(x + (size_t)row * NF);
    float4 v = xr[t];

    __shared__ float red[8];
    float s = v.x + v.y + v.z + v.w;
    #pragma unroll
    for (int o = 16; o; o >>= 1) s += __shfl_xor_sync(0xffffffffu, s, o);
    if ((t & 31) == 0) red[t >> 5] = s;
    __syncthreads();
    float tot = red[0] + red[1] + red[2] + red[3] + red[4] + red[5] + red[6] + red[7];
    float mean = tot * (1.0f / NF);
    __syncthreads();

    float dx = v.x - mean, dy = v.y - mean, dz = v.z - mean, dw = v.w - mean;
    float sq = dx * dx + dy * dy + dz * dz + dw * dw;
    #pragma unroll
    for (int o = 16; o; o >>= 1) sq += __shfl_xor_sync(0xffffffffu, sq, o);
    if ((t & 31) == 0) red[t >> 5] = sq;
    __syncthreads();
    float vtot = red[0] + red[1] + red[2] + red[3] + red[4] + red[5] + red[6] + red[7];
    float inv = rsqrtf(vtot * (1.0f / NF) + EPSLN);

    float4 gg = ((const float4*)g)[t];
    float4 bb = ((const float4*)b)[t];
    float4 out;
    out.x = dx * inv * gg.x + bb.x;
    out.y = dy * inv * gg.y + bb.y;
    out.z = dz * inv * gg.z + bb.z;
    out.w = dw * inv * gg.w + bb.w;

    if (MODE == 0) {
        ((float4*)(y + (size_t)row * NF))[t] = out;
    } else {
        size_t base = (size_t)row * NF + (size_t)t * 4;
        __half hx = __float2half_rn(out.x);
        __half hy = __float2half_rn(out.y);
        __half hz = __float2half_rn(out.z);
        __half hw = __float2half_rn(out.w);
        __half2 h0 = __halves2half2(hx, hy);
        __half2 h1 = __halves2half2(hz, hw);
        __half2 l0 = __halves2half2(__float2half_rn(out.x - __half2float(hx)),
                                    __float2half_rn(out.y - __half2float(hy)));
        __half2 l1 = __halves2half2(__float2half_rn(out.z - __half2float(hz)),
                                    __float2half_rn(out.w - __half2float(hw)));
        *(__half2*)(oh + base)     = h0;
        *(__half2*)(oh + base + 2) = h1;
        *(__half2*)(ol + base)     = l0;
        *(__half2*)(ol + base + 2) = l1;
    }
}

// ---------------------------------------------------------------------------
// GEMM: C[M,Nn] = (Ah+Al)[M,K] @ (Wh+Wl)[Nn,K]^T (+bias)(+epilogue)
// Products: AhWh + AhWl + AlWh. CTA tile 128x128, 512 threads, K-chunk 64,
// 3-stage cp.async ring.
//  - tcgen05 body (sm_103a/103f pass): SS f16 MMAs into one fp32 TMEM acc.
//  - HMMA body (all other passes): R12-exact 16-warp mma.sync path.
// EPI 0: bias, fp32 store. EPI 1: bias+relu -> fp16 hi/lo. EPI 2: C += acc+bias.
// ---------------------------------------------------------------------------
#define KC   64
// HMMA layout
#define AST  72
#define ARB  (AST*2)                  // 144 B/row
#define TILEB (128*ARB)               // 18432 B
#define STAGEB (4*TILEB)              // 73728 B
#define NSTAGE 3
#define GEMM_SMEM (NSTAGE*STAGEB)     // 221184 B (covers both layouts + align slack)
// tcgen05 layout (SW128, 128 B/row exact)
#define TILEB_T  16384
#define STAGEB_T (4*TILEB_T)          // 65536 B
#define CTRL_T   (3*STAGEB_T)         // 196608: [0:4) tmem ptr, [8:16) mbar

// HMMA loader (padded rows)
__device__ __forceinline__ void gemm_issue_chunk(
    const __half* pAh, const __half* pAl,
    const __half* pWh, const __half* pWl,
    int K, int c, uint32_t dst0, int tid) {
    const __half* srcs[4] = {pAh + (size_t)c * KC, pAl + (size_t)c * KC,
                             pWh + (size_t)c * KC, pWl + (size_t)c * KC};
    #pragma unroll
    for (int arr = 0; arr < 4; arr++) {
        const __half* p = srcs[arr];
        uint32_t d0 = dst0 + arr * TILEB;
        #pragma unroll
        for (int i = 0; i < 2; i++) {
            int idx = i * 512 + tid;
            int r = idx >> 3, cc = idx & 7;
            cp_async16(d0 + r * ARB + cc * 16, p + (size_t)r * K + cc * 8);
        }
    }
    cp_commit();
}

#if USE_TCGEN05
// tcgen05 loader (SW128 swizzle: dst = r*128 + ((cc ^ (r&7))*16))
__device__ __forceinline__ void gemm_issue_chunk_sw(
    const __half* pAh, const __half* pAl,
    const __half* pWh, const __half* pWl,
    int K, int c, uint32_t dst0, int tid) {
    const __half* srcs[4] = {pAh + (size_t)c * KC, pAl + (size_t)c * KC,
                             pWh + (size_t)c * KC, pWl + (size_t)c * KC};
    #pragma unroll
    for (int arr = 0; arr < 4; arr++) {
        const __half* p = srcs[arr];
        uint32_t d0 = dst0 + arr * TILEB_T;
        #pragma unroll
        for (int i = 0; i < 2; i++) {
            int idx = i * 512 + tid;
            int r = idx >> 3, cc = idx & 7;
            uint32_t dst = d0 + (uint32_t)r * 128u + (uint32_t)((cc ^ (r & 7)) << 4);
            cp_async16(dst, p + (size_t)r * K + cc * 8);
        }
    }
    cp_commit();
}
#endif

template <int EPI>
__global__ __launch_bounds__(512, 1)
void tc_gemm(const __half* __restrict__ Ah, const __half* __restrict__ Al,
             const __half* __restrict__ Wh, const __half* __restrict__ Wl,
             const float* __restrict__ bias, float* __restrict__ C,
             __half* __restrict__ Oh, __half* __restrict__ Ol,
             int Nn, int K) {
    extern __shared__ __align__(1024) char smem[];
    __shared__ float sbias[128];
    int tid = threadIdx.x;
    int bm = blockIdx.y * 128;
    int bn = blockIdx.x * 128;

    if (tid < 128) sbias[tid] = bias[bn + tid];

    const __half* pAh = Ah + (size_t)bm * K;
    const __half* pAl = Al + (size_t)bm * K;
    const __half* pWh = Wh + (size_t)bn * K;
    const __half* pWl = Wl + (size_t)bn * K;

    int l = tid & 31, warp = tid >> 5;
    int NC = K / KC;

#if USE_TCGEN05
    // ===================== tcgen05 path =====================
    // SW128 atoms need a 1024-aligned base; dynamic smem base may not be.
    uint32_t sb = (smem_u32(smem) + 1023u) & ~1023u;
    uint32_t ctrl = sb + CTRL_T;

    // Warp 0 allocs TMEM; other warps SKIP (no relinquish — an unordered
    // relinquish racing ahead of the alloc drops the CTA's permit and the
    // alloc never writes the TMEM pointer -> garbage tmem -> fault. This
    // matches the working test_mma.cu pattern.)
    if (tid == 0) t_mbar_init(ctrl + 8, 1);
    if (warp == 0) t_alloc(ctrl, 128);
    __syncthreads();
    uint32_t tmem;
    {
        uint32_t a;
        asm volatile("ld.shared.b32 %0, [%1];" : "=r"(a) : "r"(ctrl));
        tmem = a;
    }

    gemm_issue_chunk_sw(pAh, pAl, pWh, pWl, K, 0, sb, tid);
    gemm_issue_chunk_sw(pAh, pAl, pWh, pWl, K, 1, sb + STAGEB_T, tid);

    uint32_t mph = 0;
    int stage = 0;
    for (int c = 0; c < NC; c++) {
        if (c + 1 < NC) cp_wait<1>(); else cp_wait<0>();
        __syncthreads();
        fence_async_smem();

        uint32_t base = sb + stage * STAGEB_T;
        if (tid < 32 && elect_one()) {
            unsigned long long dAh = mkdesc(base);
            unsigned long long dAl = mkdesc(base + TILEB_T);
            unsigned long long dWh = mkdesc(base + 2 * TILEB_T);
            unsigned long long dWl = mkdesc(base + 3 * TILEB_T);
            #pragma unroll
            for (int ks = 0; ks < 4; ks++) {
                uint32_t en0 = (c > 0 || ks > 0) ? 1u : 0u;
                t_mma_f16_ss(tmem, dAh + 2 * ks, dWh + 2 * ks, TC_IDESC, en0);
                t_mma_f16_ss(tmem, dAh + 2 * ks, dWl + 2 * ks, TC_IDESC, 1u);
                t_mma_f16_ss(tmem, dAl + 2 * ks, dWh + 2 * ks, TC_IDESC, 1u);
            }
            t_commit(ctrl + 8);
        }
        // prefetch chunk c+2 into the stage drained at the barrier above
        if (c + 2 < NC) {
            int ns = stage + 2; if (ns >= NSTAGE) ns -= NSTAGE;
            gemm_issue_chunk_sw(pAh, pAl, pWh, pWl, K, c + 2, sb + ns * STAGEB_T, tid);
        }
        // synchronous MMA completion per chunk (safe accumulation + stage reuse)
        t_mbar_wait(ctrl + 8, mph); mph ^= 1;
        if (++stage >= NSTAGE) stage = 0;
    }
    t_fence_after();

    // epilogue: warp w -> TMEM subpartition (w&3) rows, column block (w>>2)*32
    {
        int sub = warp & 3;
        int cbk = (warp >> 2) * 32;
        uint32_t r[32];
        t_ld_x32(r, tmem + cbk);
        t_wait_ld();
        int m = bm + sub * 32 + l;
        size_t rowbase = (size_t)m * Nn + bn + cbk;
        if (EPI == 0) {
            #pragma unroll
            for (int j = 0; j < 8; j++) {
                float4 s = {__uint_as_float(r[4*j])   + sbias[cbk + 4*j],
                            __uint_as_float(r[4*j+1]) + sbias[cbk + 4*j+1],
                            __uint_as_float(r[4*j+2]) + sbias[cbk + 4*j+2],
                            __uint_as_float(r[4*j+3]) + sbias[cbk + 4*j+3]};
                ((float4*)(C + rowbase))[j] = s;
            }
        } else if (EPI == 2) {
            #pragma unroll
            for (int j = 0; j < 8; j++) {
                float4 old = ((float4*)(C + rowbase))[j];
                float4 s = {__uint_as_float(r[4*j])   + sbias[cbk + 4*j]   + old.x,
                            __uint_as_float(r[4*j+1]) + sbias[cbk + 4*j+1] + old.y,
                            __uint_as_float(r[4*j+2]) + sbias[cbk + 4*j+2] + old.z,
                            __uint_as_float(r[4*j+3]) + sbias[cbk + 4*j+3] + old.w};
                ((float4*)(C + rowbase))[j] = s;
            }
        } else {  // EPI 1: relu -> fp16 hi/lo split
            #pragma unroll
            for (int j = 0; j < 16; j++) {
                float v0 = fmaxf(__uint_as_float(r[2*j])   + sbias[cbk + 2*j],   0.0f);
                float v1 = fmaxf(__uint_as_float(r[2*j+1]) + sbias[cbk + 2*j+1], 0.0f);
                __half h0 = __float2half_rn(v0);
                __half h1 = __float2half_rn(v1);
                __half2 h2 = __halves2half2(h0, h1);
                __half2 l2 = __halves2half2(
                    __float2half_rn(v0 - __half2float(h0)),
                    __float2half_rn(v1 - __half2float(h1)));
                *(__half2*)(Oh + rowbase + 2*j) = h2;
                *(__half2*)(Ol + rowbase + 2*j) = l2;
            }
        }
    }
    t_fence_before();
    __syncthreads();
    if (tid == 0) t_mbar_inval(ctrl + 8);
    if (warp == 0) t_dealloc(tmem, 128);

#else
    // ===================== HMMA fallback (R12-exact) =====================
    uint32_t sb = smem_u32(smem);
    int wm = warp >> 2, wn = warp & 3;       // 4x4 warps, warp tile 32x32

    float acc[2][4][4];
    uint32_t cor[2][4][2];
    #pragma unroll
    for (int i = 0; i < 2; i++)
        #pragma unroll
        for (int j = 0; j < 4; j++) {
            #pragma unroll
            for (int k = 0; k < 4; k++) acc[i][j][k] = 0.0f;
            cor[i][j][0] = 0u; cor[i][j][1] = 0u;
        }

    int arow  = wm * 32 + (l & 15);
    int acolb = (l >> 4) * 16;
    int brow  = wn * 32 + ((l >> 4) & 1) * 8 + (l & 7);
    int bcolb = ((l >> 3) & 1) * 16;

    gemm_issue_chunk(pAh, pAl, pWh, pWl, K, 0, sb, tid);
    gemm_issue_chunk(pAh, pAl, pWh, pWl, K, 1, sb + STAGEB, tid);

    int stage = 0;
    for (int c = 0; c < NC; c++) {
        if (c + 1 < NC) cp_wait<1>(); else cp_wait<0>();
        __syncthreads();

        uint32_t sA  = sb + stage * STAGEB;
        uint32_t sAl = sA + TILEB;
        uint32_t sW  = sA + 2 * TILEB;
        uint32_t sWl = sA + 3 * TILEB;

        #pragma unroll
        for (int ks = 0; ks < KC / 16; ks++) {
            uint32_t ah[2][4], al4[2][4], wh[2][4], wl4[2][4];
            #pragma unroll
            for (int i = 0; i < 2; i++) {
                uint32_t off = (uint32_t)(arow + i * 16) * ARB + ks * 32 + acolb;
                ldsm_x4(ah[i],  sA  + off);
                ldsm_x4(al4[i], sAl + off);
            }
            #pragma unroll
            for (int jp = 0; jp < 2; jp++) {
                uint32_t off = (uint32_t)(brow + jp * 16) * ARB + ks * 32 + bcolb;
                ldsm_x4(wh[jp],  sW  + off);
                ldsm_x4(wl4[jp], sWl + off);
            }
            #pragma unroll
            for (int i = 0; i < 2; i++)
                #pragma unroll
                for (int j = 0; j < 4; j++) {
                    const uint32_t* bh = &wh[j >> 1][(j & 1) * 2];
                    const uint32_t* bl = &wl4[j >> 1][(j & 1) * 2];
                    mma_f32acc(acc[i][j], ah[i], bh);
                    mma_f16acc(cor[i][j], ah[i], bl);
                    mma_f16acc(cor[i][j], al4[i], bh);
                }
        }

        if (c + 2 < NC) {
            int ns = stage + 2; if (ns >= NSTAGE) ns -= NSTAGE;
            gemm_issue_chunk(pAh, pAl, pWh, pWl, K, c + 2, sb + ns * STAGEB, tid);
        }
        if (++stage >= NSTAGE) stage = 0;
    }

    int r0 = bm + wm * 32 + (l >> 2);
    int cb = wn * 32 + 2 * (l & 3);
    #pragma unroll
    for (int i = 0; i < 2; i++) {
        #pragma unroll
        for (int j = 0; j < 4; j++) {
            int col = cb + j * 8;
            float b0 = sbias[col], b1 = sbias[col + 1];
            #pragma unroll
            for (int half = 0; half < 2; half++) {
                __half2 ch = *(__half2*)&cor[i][j][half];
                float2 cf = __half22float2(ch);
                int m = r0 + i * 16 + half * 8;
                float v0 = acc[i][j][2 * half]     + cf.x + b0;
                float v1 = acc[i][j][2 * half + 1] + cf.y + b1;
                size_t idx = (size_t)m * Nn + bn + col;
                if (EPI == 0) {
                    float2 s = {v0, v1};
                    *(float2*)(C + idx) = s;
                } else if (EPI == 2) {
                    float2 old = *(const float2*)(C + idx);
                    float2 s = {v0 + old.x, v1 + old.y};
                    *(float2*)(C + idx) = s;
                } else {
                    v0 = fmaxf(v0, 0.0f);
                    v1 = fmaxf(v1, 0.0f);
                    __half h0 = __float2half_rn(v0);
                    __half h1 = __float2half_rn(v1);
                    __half2 h2 = __halves2half2(h0, h1);
                    __half2 l2 = __halves2half2(
                        __float2half_rn(v0 - __half2float(h0)),
                        __float2half_rn(v1 - __half2float(h1)));
                    *(__half2*)(Oh + idx) = h2;
                    *(__half2*)(Ol + idx) = l2;
                }
            }
        }
    }
#endif
}

// ---------------------------------------------------------------------------
// Fused attention: one CTA per (b,h), 512 threads, K/V resident in SMEM.
// ---------------------------------------------------------------------------
#define KST 68
#define ATTN_SMEM ((SEQ*KST + SEQ*HD + 16*4*SEQ) * 4)

__global__ __launch_bounds__(512, 1) void attn_kernel(const float* __restrict__ qkv,
                                                      const float* __restrict__ mask,
                                                      __half* __restrict__ oh,
                                                      __half* __restrict__ ol) {
    extern __shared__ __align__(16) float sm[];
    float* Ks = sm;
    float* Vs = Ks + SEQ * KST;
    float* Ps = Vs + SEQ * HD;

    int bh = blockIdx.x;
    int b  = bh >> 4;
    int h  = bh & 15;
    int tid = threadIdx.x;

    for (int idx = tid; idx < SEQ * 16; idx += 512) {
        int s = idx >> 4;
        int c = (idx & 15) << 2;
        size_t base = ((size_t)s * BATCH + b) * (3 * PD) + (size_t)h * HD + c;
        float4 k4 = *(const float4*)(qkv + base + PD);
        float4 v4 = *(const float4*)(qkv + base + 2 * PD);
        *(float4*)(Ks + s * KST + c) = k4;
        *(float4*)(Vs + s * HD + c) = v4;
    }
    __syncthreads();

    int warp = tid >> 5, lane = tid & 31;
    float* Pw = Ps + warp * 4 * SEQ;
    const size_t qtstep = (size_t)BATCH * 3 * PD;

    for (int it = 0; it < 4; it++) {
        int t0 = warp * 16 + it * 4;
        const float* qp0 = qkv + ((size_t)t0 * BATCH + b) * (3 * PD) + (size_t)h * HD;

        unsigned long long sc2[4][8];
        #pragma unroll
        for (int q = 0; q < 4; q++)
            #pragma unroll
            for (int j = 0; j < 8; j++) sc2[q][j] = 0ull;

        #pragma unroll 2
        for (int d4 = 0; d4 < 16; d4++) {
            const float* qb = qp0 + 4 * d4;
            ulonglong2 aq0 = *(const ulonglong2*)(qb);
            ulonglong2 aq1 = *(const ulonglong2*)(qb + qtstep);
            ulonglong2 aq2 = *(const ulonglong2*)(qb + 2 * qtstep);
            ulonglong2 aq3 = *(const ulonglong2*)(qb + 3 * qtstep);
            #pragma unroll
            for (int j = 0; j < 8; j++) {
                int s = lane + 32 * j;
                ulonglong2 k2 = *(const ulonglong2*)(Ks + s * KST + 4 * d4);
                sc2[0][j] = fma2(aq0.x, k2.x, sc2[0][j]);
                sc2[0][j] = fma2(aq0.y, k2.y, sc2[0][j]);
                sc2[1][j] = fma2(aq1.x, k2.x, sc2[1][j]);
                sc2[1][j] = fma2(aq1.y, k2.y, sc2[1][j]);
                sc2[2][j] = fma2(aq2.x, k2.x, sc2[2][j]);
                sc2[2][j] = fma2(aq2.y, k2.y, sc2[2][j]);
                sc2[3][j] = fma2(aq3.x, k2.x, sc2[3][j]);
                sc2[3][j] = fma2(aq3.y, k2.y, sc2[3][j]);
            }
        }

        #pragma unroll
        for (int q = 0; q < 4; q++) {
            float pr[8];
            const float* mrow = mask + (size_t)(t0 + q) * SEQ;
            #pragma unroll
            for (int j = 0; j < 8; j++) {
                float lo, hi;
                unpack2(sc2[q][j], lo, hi);
                pr[j] = (lo + hi) * 0.125f + mrow[lane + 32 * j];
            }
            float mx = pr[0];
            #pragma unroll
            for (int j = 1; j < 8; j++) mx = fmaxf(mx, pr[j]);
            #pragma unroll
            for (int o = 16; o; o >>= 1) mx = fmaxf(mx, __shfl_xor_sync(0xffffffffu, mx, o));
            float sum = 0.0f;
            #pragma unroll
            for (int j = 0; j < 8; j++) { pr[j] = __expf(pr[j] - mx); sum += pr[j]; }
            #pragma unroll
            for (int o = 16; o; o >>= 1) sum += __shfl_xor_sync(0xffffffffu, sum, o);
            float inv = 1.0f / sum;
            #pragma unroll
            for (int j = 0; j < 8; j++) Pw[q * SEQ + lane + 32 * j] = pr[j] * inv;
        }
        __syncwarp();

        float2 acc0 = {0, 0}, acc1 = {0, 0}, acc2v = {0, 0}, acc3 = {0, 0};
        const float* vcol = Vs + 2 * lane;
        for (int s = 0; s < SEQ; s++) {
            float2 v2 = *(const float2*)(vcol + s * HD);
            float p0 = Pw[s];
            float p1 = Pw[SEQ + s];
            float p2 = Pw[2 * SEQ + s];
            float p3 = Pw[3 * SEQ + s];
            acc0.x = fmaf(p0, v2.x, acc0.x); acc0.y = fmaf(p0, v2.y, acc0.y);
            acc1.x = fmaf(p1, v2.x, acc1.x); acc1.y = fmaf(p1, v2.y, acc1.y);
            acc2v.x = fmaf(p2, v2.x, acc2v.x); acc2v.y = fmaf(p2, v2.y, acc2v.y);
            acc3.x = fmaf(p3, v2.x, acc3.x); acc3.y = fmaf(p3, v2.y, acc3.y);
        }
        size_t obase = ((size_t)t0 * BATCH + b) * PD + (size_t)h * HD + 2 * lane;
        size_t ostep = (size_t)BATCH * PD;
        float2 accs[4] = {acc0, acc1, acc2v, acc3};
        #pragma unroll
        for (int q = 0; q < 4; q++) {
            size_t oidx = obase + q * ostep;
            __half hx = __float2half_rn(accs[q].x);
            __half hy = __float2half_rn(accs[q].y);
            __half2 h2 = __halves2half2(hx, hy);
            __half2 l2 = __halves2half2(
                __float2half_rn(accs[q].x - __half2float(hx)),
                __float2half_rn(accs[q].y - __half2float(hy)));
            *(__half2*)(oh + oidx) = h2;
            *(__half2*)(ol + oidx) = l2;
        }
        __syncwarp();
    }
}

// ---------------------------------------------------------------------------
// Host orchestration
// ---------------------------------------------------------------------------
extern "C" void kernel_launch(void* const* d_in, const int* in_sizes, int n_in,
                              void* d_out, int out_size) {
    const float* src  = (const float*)d_in[0];
    const float* mask = (const float*)d_in[1];
    const float* Wqkv = (const float*)d_in[2];
    const float* bqkv = (const float*)d_in[3];
    const float* Wo   = (const float*)d_in[4];
    const float* bo   = (const float*)d_in[5];
    const float* ln1g = (const float*)d_in[6];
    const float* ln1b = (const float*)d_in[7];
    const float* ln2g = (const float*)d_in[8];
    const float* ln2b = (const float*)d_in[9];
    const float* W1   = (const float*)d_in[10];
    const float* b1   = (const float*)d_in[11];
    const float* W2   = (const float*)d_in[12];
    const float* b2   = (const float*)d_in[13];
    const float* lnfg = (const float*)d_in[14];
    const float* lnfb = (const float*)d_in[15];

    float* x = (float*)d_out;

    void *pqkv, *pah, *pal, *pffh, *pffl, *pwh, *pwl;
    cudaGetSymbolAddress(&pqkv, g_qkv);
    cudaGetSymbolAddress(&pah, g_ah);
    cudaGetSymbolAddress(&pal, g_al);
    cudaGetSymbolAddress(&pffh, g_ffh);
    cudaGetSymbolAddress(&pffl, g_ffl);
    cudaGetSymbolAddress(&pwh, g_wh);
    cudaGetSymbolAddress(&pwl, g_wl);
    float* qk = (float*)pqkv;
    __half* ah  = (__half*)pah;
    __half* al  = (__half*)pal;
    __half* ffh = (__half*)pffh;
    __half* ffl = (__half*)pffl;
    __half* wh  = (__half*)pwh;
    __half* wl  = (__half*)pwl;

    cudaFuncSetAttribute(attn_kernel, cudaFuncAttributeMaxDynamicSharedMemorySize,
                         ATTN_SMEM);
    cudaFuncSetAttribute(tc_gemm<0>, cudaFuncAttributeMaxDynamicSharedMemorySize,
                         GEMM_SMEM);
    cudaFuncSetAttribute(tc_gemm<1>, cudaFuncAttributeMaxDynamicSharedMemorySize,
                         GEMM_SMEM);
    cudaFuncSetAttribute(tc_gemm<2>, cudaFuncAttributeMaxDynamicSharedMemorySize,
                         GEMM_SMEM);

    // x = src
    copy_kernel<<<ROWS * NF / (256 * 4), 256>>>(src, x);

    dim3 gQKV(3 * PD / 128, ROWS / 128);   // (24, 64)
    dim3 gWO(NF / 128, ROWS / 128);        // (8, 64)
    dim3 gW1(FF / 128, ROWS / 128);        // (32, 64)
    dim3 gW2(NF / 128, ROWS / 128);        // (8, 64)

    for (int l = 0; l < LAYERS; l++) {
        const float* wqkv = Wqkv + (size_t)l * 3 * PD * NF;
        const float* bq   = bqkv + (size_t)l * 3 * PD;
        const float* wo   = Wo   + (size_t)l * NF * PD;
        const float* bo_  = bo   + (size_t)l * NF;
        const float* w1   = W1   + (size_t)l * FF * NF;
        const float* bb1  = b1   + (size_t)l * FF;
        const float* w2   = W2   + (size_t)l * NF * FF;
        const float* bb2  = b2   + (size_t)l * NF;

        // --- attention block ---
        ln_kernel<1><<<ROWS, 256>>>(x, ln1g + (size_t)l * NF, ln1b + (size_t)l * NF,
                                    nullptr, ah, al);
        convw_kernel<<<(3 * PD * NF) / 1024, 256>>>(wqkv, wh, wl);
        tc_gemm<0><<<gQKV, 512, GEMM_SMEM>>>(ah, al, wh, wl, bq, qk,
                                             nullptr, nullptr, 3 * PD, NF);
        attn_kernel<<<BATCH * NH, 512, ATTN_SMEM>>>(qk, mask, ah, al);
        convw_kernel<<<(NF * PD) / 1024, 256>>>(wo, wh, wl);
        tc_gemm<2><<<gWO, 512, GEMM_SMEM>>>(ah, al, wh, wl, bo_, x,
                                            nullptr, nullptr, NF, PD);

        // --- FFN block ---
        ln_kernel<1><<<ROWS, 256>>>(x, ln2g + (size_t)l * NF, ln2b + (size_t)l * NF,
                                    nullptr, ah, al);
        convw_kernel<<<(FF * NF) / 1024, 256>>>(w1, wh, wl);
        tc_gemm<1><<<gW1, 512, GEMM_SMEM>>>(ah, al, wh, wl, bb1, nullptr,
                                            ffh, ffl, FF, NF);
        convw_kernel<<<(NF * FF) / 1024, 256>>>(w2, wh, wl);
        tc_gemm<2><<<gW2, 512, GEMM_SMEM>>>(ffh, ffl, wh, wl, bb2, x,
                                            nullptr, nullptr, NF, FF);
    }

    // final LN (fp32, in-place on d_out)
    ln_kernel<0><<<ROWS, 256>>>(x, lnfg, lnfb, x, nullptr, nullptr);
}

// round 17
// speedup vs baseline: 1.8561x; 1.0291x over previous
#include <cuda_runtime.h>
#include <cuda_fp16.h>
#include <cstdint>

// ---------------------------------------------------------------------------
// Arch-specific feature gate: tcgen05 compiles ONLY in sm_103a/103f passes.
// The plain sm_103 ptxas pass sees the HMMA fallback (R12-exact).
// ---------------------------------------------------------------------------
#if (defined(__CUDA_ARCH_SPECIFIC__) && (__CUDA_ARCH_SPECIFIC__ == 1030)) || \
    (defined(__CUDA_ARCH_FAMILY_SPECIFIC__) && (__CUDA_ARCH_FAMILY_SPECIFIC__ == 1030)) || \
    defined(__CUDA_ARCH_FEAT_SM103_ALL)
#define USE_TCGEN05 1
#else
#define USE_TCGEN05 0
#endif

// ---------------------------------------------------------------------------
// Problem constants
// ---------------------------------------------------------------------------
#define LAYERS 6
#define SEQ    256
#define BATCH  32
#define NF     1024
#define NH     16
#define HD     64
#define PD     1024
#define FF     4096
#define ROWS   (SEQ*BATCH)     // 8192
#define EPSLN  1e-5f

// ---------------------------------------------------------------------------
// Scratch (device globals; allocation-free per harness rules)
// ---------------------------------------------------------------------------
__device__ float   g_qkv[(size_t)ROWS * 3 * PD];
__device__ __half  g_ah [(size_t)ROWS * NF];
__device__ __half  g_al [(size_t)ROWS * NF];
__device__ __half  g_ffh[(size_t)ROWS * FF];
__device__ __half  g_ffl[(size_t)ROWS * FF];
__device__ __half  g_wh [(size_t)FF * NF];
__device__ __half  g_wl [(size_t)FF * NF];

// ---------------------------------------------------------------------------
// PTX helpers (base sm_103 instruction set)
// ---------------------------------------------------------------------------
__device__ __forceinline__ uint32_t smem_u32(const void* p) {
    uint32_t a;
    asm("{ .reg .u64 t; cvta.to.shared.u64 t, %1; cvt.u32.u64 %0, t; }"
        : "=r"(a) : "l"(p));
    return a;
}
__device__ __forceinline__ void cp_async16(uint32_t saddr, const void* gaddr) {
    asm volatile("cp.async.cg.shared.global [%0], [%1], 16;"
                 :: "r"(saddr), "l"(gaddr) : "memory");
}
__device__ __forceinline__ void cp_commit() {
    asm volatile("cp.async.commit_group;" ::: "memory");
}
template <int N>
__device__ __forceinline__ void cp_wait() {
    asm volatile("cp.async.wait_group %0;" :: "n"(N) : "memory");
}
__device__ __forceinline__ void ldsm_x4(uint32_t* r, uint32_t addr) {
    asm volatile("ldmatrix.sync.aligned.m8n8.x4.shared.b16 {%0,%1,%2,%3}, [%4];"
                 : "=r"(r[0]), "=r"(r[1]), "=r"(r[2]), "=r"(r[3]) : "r"(addr));
}
__device__ __forceinline__ void mma_f32acc(float* c, const uint32_t* a, const uint32_t* b) {
    asm volatile(
        "mma.sync.aligned.m16n8k16.row.col.f32.f16.f16.f32 "
        "{%0,%1,%2,%3}, {%4,%5,%6,%7}, {%8,%9}, {%0,%1,%2,%3};"
        : "+f"(c[0]), "+f"(c[1]), "+f"(c[2]), "+f"(c[3])
        : "r"(a[0]), "r"(a[1]), "r"(a[2]), "r"(a[3]), "r"(b[0]), "r"(b[1]));
}
__device__ __forceinline__ void mma_f16acc(uint32_t* c, const uint32_t* a, const uint32_t* b) {
    asm volatile(
        "mma.sync.aligned.m16n8k16.row.col.f16.f16.f16.f16 "
        "{%0,%1}, {%2,%3,%4,%5}, {%6,%7}, {%0,%1};"
        : "+r"(c[0]), "+r"(c[1])
        : "r"(a[0]), "r"(a[1]), "r"(a[2]), "r"(a[3]), "r"(b[0]), "r"(b[1]));
}

// f32x2 helpers for attention
__device__ __forceinline__ unsigned long long fma2(unsigned long long a,
                                                   unsigned long long b,
                                                   unsigned long long c) {
    unsigned long long d;
    asm("fma.rn.f32x2 %0, %1, %2, %3;" : "=l"(d) : "l"(a), "l"(b), "l"(c));
    return d;
}
__device__ __forceinline__ void unpack2(unsigned long long v, float& lo, float& hi) {
    asm("mov.b64 {%0, %1}, %2;" : "=f"(lo), "=f"(hi) : "l"(v));
}

#if USE_TCGEN05
// ---------------------------------------------------------------------------
// tcgen05 helpers (compiled only in sm_103a/103f passes)
// ---------------------------------------------------------------------------
__device__ __forceinline__ bool elect_one() {
    uint32_t p;
    asm volatile("{\n\t.reg .pred P;\n\telect.sync _|P, 0xFFFFFFFF;\n\t"
                 "selp.b32 %0, 1, 0, P;\n\t}" : "=r"(p));
    return p != 0;
}
__device__ __forceinline__ void t_mbar_init(uint32_t mbar, uint32_t cnt) {
    asm volatile("mbarrier.init.shared.b64 [%0], %1;" :: "r"(mbar), "r"(cnt) : "memory");
}
__device__ __forceinline__ void t_mbar_inval(uint32_t mbar) {
    asm volatile("mbarrier.inval.shared.b64 [%0];" :: "r"(mbar) : "memory");
}
__device__ __forceinline__ void t_mbar_wait(uint32_t mbar, uint32_t phase) {
    asm volatile(
        "{\n\t.reg .pred P;\n\t"
        "WL_%=:\n\t"
        "mbarrier.try_wait.parity.acquire.cta.shared::cta.b64 P, [%0], %1, 0x989680;\n\t"
        "@P bra.uni WD_%=;\n\t"
        "bra.uni WL_%=;\n\t"
        "WD_%=:\n\t}"
        :: "r"(mbar), "r"(phase) : "memory");
}
__device__ __forceinline__ void t_alloc(uint32_t smem_dst, uint32_t ncols) {
    asm volatile("tcgen05.alloc.cta_group::1.sync.aligned.shared::cta.b32 [%0], %1;"
                 :: "r"(smem_dst), "r"(ncols) : "memory");
}
__device__ __forceinline__ void t_dealloc(uint32_t tmem, uint32_t ncols) {
    asm volatile("tcgen05.dealloc.cta_group::1.sync.aligned.b32 %0, %1;"
                 :: "r"(tmem), "r"(ncols));
}
__device__ __forceinline__ void t_mma_f16_ss(uint32_t d, unsigned long long a,
                                             unsigned long long b, uint32_t idesc,
                                             uint32_t en) {
    asm volatile(
        "{\n\t.reg .pred p;\n\t"
        "setp.ne.u32 p, %4, 0;\n\t"
        "tcgen05.mma.cta_group::1.kind::f16 [%0], %1, %2, %3, {%5, %5, %5, %5}, p;\n\t}"
        :: "r"(d), "l"(a), "l"(b), "r"(idesc), "r"(en), "r"(0u)
        : "memory");
}
__device__ __forceinline__ void t_commit(uint32_t mbar) {
    asm volatile(
        "tcgen05.commit.cta_group::1.mbarrier::arrive::one.shared::cluster.b64 [%0];"
        :: "r"(mbar) : "memory");
}
__device__ __forceinline__ void t_ld_x32(uint32_t* r, uint32_t addr) {
    asm volatile(
        "tcgen05.ld.sync.aligned.32x32b.x32.b32 "
        "{%0, %1, %2, %3, %4, %5, %6, %7, "
        " %8, %9, %10, %11, %12, %13, %14, %15, "
        " %16, %17, %18, %19, %20, %21, %22, %23, "
        " %24, %25, %26, %27, %28, %29, %30, %31}, [%32];"
        : "=r"(r[0]),  "=r"(r[1]),  "=r"(r[2]),  "=r"(r[3]),
          "=r"(r[4]),  "=r"(r[5]),  "=r"(r[6]),  "=r"(r[7]),
          "=r"(r[8]),  "=r"(r[9]),  "=r"(r[10]), "=r"(r[11]),
          "=r"(r[12]), "=r"(r[13]), "=r"(r[14]), "=r"(r[15]),
          "=r"(r[16]), "=r"(r[17]), "=r"(r[18]), "=r"(r[19]),
          "=r"(r[20]), "=r"(r[21]), "=r"(r[22]), "=r"(r[23]),
          "=r"(r[24]), "=r"(r[25]), "=r"(r[26]), "=r"(r[27]),
          "=r"(r[28]), "=r"(r[29]), "=r"(r[30]), "=r"(r[31])
        : "r"(addr));
}
__device__ __forceinline__ void t_wait_ld() {
    asm volatile("tcgen05.wait::ld.sync.aligned;" ::: "memory");
}
__device__ __forceinline__ void t_fence_after() {
    asm volatile("tcgen05.fence::after_thread_sync;" ::: "memory");
}
__device__ __forceinline__ void t_fence_before() {
    asm volatile("tcgen05.fence::before_thread_sync;" ::: "memory");
}
__device__ __forceinline__ void fence_async_smem() {
    asm volatile("fence.proxy.async.shared::cta;" ::: "memory");
}
// SW128 smem descriptor: layout=SW128, version=1, SBO=64, LBO=1
#define DESC_BASE_SW128 0x4000404000010000ULL
__device__ __forceinline__ unsigned long long mkdesc(uint32_t smem_addr) {
    return DESC_BASE_SW128 | (unsigned long long)((smem_addr >> 4) & 0x3FFF);
}
// idesc kind::f16: f32 acc (1<<4), atype=btype=f16 (0), N=128 (16<<17), M=128 (8<<24)
#define TC_IDESC 0x08200010u
#endif // USE_TCGEN05

// ---------------------------------------------------------------------------
// Utility kernels
// ---------------------------------------------------------------------------
__global__ __launch_bounds__(256) void copy_kernel(const float* __restrict__ src,
                                                   float* __restrict__ dst) {
    size_t i = (size_t)blockIdx.x * 256 + threadIdx.x;
    ((float4*)dst)[i] = ((const float4*)src)[i];
}

// fp32 -> fp16 hi/lo split (weights)
__global__ __launch_bounds__(256) void convw_kernel(const float* __restrict__ w,
                                                    __half* __restrict__ hi,
                                                    __half* __restrict__ lo) {
    size_t i = (size_t)blockIdx.x * 256 + threadIdx.x;
    float4 v = ((const float4*)w)[i];
    __half hx = __float2half_rn(v.x);
    __half hy = __float2half_rn(v.y);
    __half hz = __float2half_rn(v.z);
    __half hw = __float2half_rn(v.w);
    __half2 h0 = __halves2half2(hx, hy);
    __half2 h1 = __halves2half2(hz, hw);
    __half2 l0 = __halves2half2(__float2half_rn(v.x - __half2float(hx)),
                                __float2half_rn(v.y - __half2float(hy)));
    __half2 l1 = __halves2half2(__float2half_rn(v.z - __half2float(hz)),
                                __float2half_rn(v.w - __half2float(hw)));
    ((__half2*)hi)[2 * i]     = h0;
    ((__half2*)hi)[2 * i + 1] = h1;
    ((__half2*)lo)[2 * i]     = l0;
    ((__half2*)lo)[2 * i + 1] = l1;
}

// ---------------------------------------------------------------------------
// LayerNorm over N=1024. MODE 0: fp32 out. MODE 1: fp16 hi/lo out.
// ---------------------------------------------------------------------------
template <int MODE>
__global__ __launch_bounds__(256) void ln_kernel(const float* __restrict__ x,
                                                 const float* __restrict__ g,
                                                 const float* __restrict__ b,
                                                 float* __restrict__ y,
                                                 __half* __restrict__ oh,
                                                 __half* __restrict__ ol) {
    int row = blockIdx.x;
    int t   = threadIdx.x;
    const float4* xr = (const float4*)(x + (size_t)row * NF);
    float4 v = xr[t];

    __shared__ float red[8];
    float s = v.x + v.y + v.z + v.w;
    #pragma unroll
    for (int o = 16; o; o >>= 1) s += __shfl_xor_sync(0xffffffffu, s, o);
    if ((t & 31) == 0) red[t >> 5] = s;
    __syncthreads();
    float tot = red[0] + red[1] + red[2] + red[3] + red[4] + red[5] + red[6] + red[7];
    float mean = tot * (1.0f / NF);
    __syncthreads();

    float dx = v.x - mean, dy = v.y - mean, dz = v.z - mean, dw = v.w - mean;
    float sq = dx * dx + dy * dy + dz * dz + dw * dw;
    #pragma unroll
    for (int o = 16; o; o >>= 1) sq += __shfl_xor_sync(0xffffffffu, sq, o);
    if ((t & 31) == 0) red[t >> 5] = sq;
    __syncthreads();
    float vtot = red[0] + red[1] + red[2] + red[3] + red[4] + red[5] + red[6] + red[7];
    float inv = rsqrtf(vtot * (1.0f / NF) + EPSLN);

    float4 gg = ((const float4*)g)[t];
    float4 bb = ((const float4*)b)[t];
    float4 out;
    out.x = dx * inv * gg.x + bb.x;
    out.y = dy * inv * gg.y + bb.y;
    out.z = dz * inv * gg.z + bb.z;
    out.w = dw * inv * gg.w + bb.w;

    if (MODE == 0) {
        ((float4*)(y + (size_t)row * NF))[t] = out;
    } else {
        size_t base = (size_t)row * NF + (size_t)t * 4;
        __half hx = __float2half_rn(out.x);
        __half hy = __float2half_rn(out.y);
        __half hz = __float2half_rn(out.z);
        __half hw = __float2half_rn(out.w);
        __half2 h0 = __halves2half2(hx, hy);
        __half2 h1 = __halves2half2(hz, hw);
        __half2 l0 = __halves2half2(__float2half_rn(out.x - __half2float(hx)),
                                    __float2half_rn(out.y - __half2float(hy)));
        __half2 l1 = __halves2half2(__float2half_rn(out.z - __half2float(hz)),
                                    __float2half_rn(out.w - __half2float(hw)));
        *(__half2*)(oh + base)     = h0;
        *(__half2*)(oh + base + 2) = h1;
        *(__half2*)(ol + base)     = l0;
        *(__half2*)(ol + base + 2) = l1;
    }
}

// ---------------------------------------------------------------------------
// GEMM: C[M,Nn] = (Ah+Al)[M,K] @ (Wh+Wl)[Nn,K]^T (+bias)(+epilogue)
// Products: AhWh + AhWl + AlWh. CTA tile 128x128, 512 threads, K-chunk 64,
// 3-stage cp.async ring.
//  - tcgen05 body (sm_103a/103f pass): SS f16 MMAs into one fp32 TMEM acc,
//    LAG-1 commit/wait pipelining with TWO alternating mbarriers (chunk c
//    commits to mbar[c&1]; each barrier flips once per 2 chunks, killing the
//    parity-ABA deadlock a single barrier has at lag 1).
//  - HMMA body (all other passes): R12-exact 16-warp mma.sync path.
// EPI 0: bias, fp32 store. EPI 1: bias+relu -> fp16 hi/lo. EPI 2: C += acc+bias.
// ---------------------------------------------------------------------------
#define KC   64
// HMMA layout
#define AST  72
#define ARB  (AST*2)                  // 144 B/row
#define TILEB (128*ARB)               // 18432 B
#define STAGEB (4*TILEB)              // 73728 B
#define NSTAGE 3
#define GEMM_SMEM (NSTAGE*STAGEB)     // 221184 B (covers both layouts + align slack)
// tcgen05 layout (SW128, 128 B/row exact)
#define TILEB_T  16384
#define STAGEB_T (4*TILEB_T)          // 65536 B
#define CTRL_T   (3*STAGEB_T)         // 196608: [0:4) tmem ptr, [8:24) mbar0/mbar1

// HMMA loader (padded rows)
__device__ __forceinline__ void gemm_issue_chunk(
    const __half* pAh, const __half* pAl,
    const __half* pWh, const __half* pWl,
    int K, int c, uint32_t dst0, int tid) {
    const __half* srcs[4] = {pAh + (size_t)c * KC, pAl + (size_t)c * KC,
                             pWh + (size_t)c * KC, pWl + (size_t)c * KC};
    #pragma unroll
    for (int arr = 0; arr < 4; arr++) {
        const __half* p = srcs[arr];
        uint32_t d0 = dst0 + arr * TILEB;
        #pragma unroll
        for (int i = 0; i < 2; i++) {
            int idx = i * 512 + tid;
            int r = idx >> 3, cc = idx & 7;
            cp_async16(d0 + r * ARB + cc * 16, p + (size_t)r * K + cc * 8);
        }
    }
    cp_commit();
}

#if USE_TCGEN05
// tcgen05 loader (SW128 swizzle: dst = r*128 + ((cc ^ (r&7))*16))
__device__ __forceinline__ void gemm_issue_chunk_sw(
    const __half* pAh, const __half* pAl,
    const __half* pWh, const __half* pWl,
    int K, int c, uint32_t dst0, int tid) {
    const __half* srcs[4] = {pAh + (size_t)c * KC, pAl + (size_t)c * KC,
                             pWh + (size_t)c * KC, pWl + (size_t)c * KC};
    #pragma unroll
    for (int arr = 0; arr < 4; arr++) {
        const __half* p = srcs[arr];
        uint32_t d0 = dst0 + arr * TILEB_T;
        #pragma unroll
        for (int i = 0; i < 2; i++) {
            int idx = i * 512 + tid;
            int r = idx >> 3, cc = idx & 7;
            uint32_t dst = d0 + (uint32_t)r * 128u + (uint32_t)((cc ^ (r & 7)) << 4);
            cp_async16(dst, p + (size_t)r * K + cc * 8);
        }
    }
    cp_commit();
}
#endif

template <int EPI>
__global__ __launch_bounds__(512, 1)
void tc_gemm(const __half* __restrict__ Ah, const __half* __restrict__ Al,
             const __half* __restrict__ Wh, const __half* __restrict__ Wl,
             const float* __restrict__ bias, float* __restrict__ C,
             __half* __restrict__ Oh, __half* __restrict__ Ol,
             int Nn, int K) {
    extern __shared__ __align__(1024) char smem[];
    __shared__ float sbias[128];
    int tid = threadIdx.x;
    int bm = blockIdx.y * 128;
    int bn = blockIdx.x * 128;

    if (tid < 128) sbias[tid] = bias[bn + tid];

    const __half* pAh = Ah + (size_t)bm * K;
    const __half* pAl = Al + (size_t)bm * K;
    const __half* pWh = Wh + (size_t)bn * K;
    const __half* pWl = Wl + (size_t)bn * K;

    int l = tid & 31, warp = tid >> 5;
    int NC = K / KC;

#if USE_TCGEN05
    // ===================== tcgen05 path =====================
    // SW128 atoms need a 1024-aligned base; dynamic smem base may not be.
    uint32_t sb = (smem_u32(smem) + 1023u) & ~1023u;
    uint32_t ctrl = sb + CTRL_T;

    // Warp 0 allocs TMEM; other warps SKIP (no relinquish — see R15 note).
    if (tid == 0) { t_mbar_init(ctrl + 8, 1); t_mbar_init(ctrl + 16, 1); }
    if (warp == 0) t_alloc(ctrl, 128);
    __syncthreads();
    uint32_t tmem;
    {
        uint32_t a;
        asm volatile("ld.shared.b32 %0, [%1];" : "=r"(a) : "r"(ctrl));
        tmem = a;
    }

    gemm_issue_chunk_sw(pAh, pAl, pWh, pWl, K, 0, sb, tid);
    gemm_issue_chunk_sw(pAh, pAl, pWh, pWl, K, 1, sb + STAGEB_T, tid);

    // LAG-1 pipelined mainloop (two alternating commit barriers):
    //   chunk c commits to mbar[c&1]; the (c>>1)-th commit on that barrier
    //   completes phase parity (c>>1)&1. Waiting for chunk c-1 before
    //   refilling stage (c+2)%3 == (c-1)%3 overlaps MMA c with chunk c+1's
    //   cp_wait/barrier/loads. ABA needs a 4-chunk lag -> impossible here.
    int stage = 0;
    for (int c = 0; c < NC; c++) {
        if (c + 1 < NC) cp_wait<1>(); else cp_wait<0>();
        __syncthreads();
        fence_async_smem();

        uint32_t base = sb + stage * STAGEB_T;
        if (tid < 32 && elect_one()) {
            unsigned long long dAh = mkdesc(base);
            unsigned long long dAl = mkdesc(base + TILEB_T);
            unsigned long long dWh = mkdesc(base + 2 * TILEB_T);
            unsigned long long dWl = mkdesc(base + 3 * TILEB_T);
            #pragma unroll
            for (int ks = 0; ks < 4; ks++) {
                uint32_t en0 = (c > 0 || ks > 0) ? 1u : 0u;
                t_mma_f16_ss(tmem, dAh + 2 * ks, dWh + 2 * ks, TC_IDESC, en0);
                t_mma_f16_ss(tmem, dAh + 2 * ks, dWl + 2 * ks, TC_IDESC, 1u);
                t_mma_f16_ss(tmem, dAl + 2 * ks, dWh + 2 * ks, TC_IDESC, 1u);
            }
            t_commit(ctrl + 8 + 8 * (uint32_t)(c & 1));
        }
        if (c + 2 < NC) {
            // Stage (c+2)%3 held chunk c-1; wait for its commit before refill.
            if (c >= 1)
                t_mbar_wait(ctrl + 8 + 8 * (uint32_t)((c - 1) & 1),
                            (uint32_t)(((c - 1) >> 1) & 1));
            int ns = stage + 2; if (ns >= NSTAGE) ns -= NSTAGE;
            gemm_issue_chunk_sw(pAh, pAl, pWh, pWl, K, c + 2, sb + ns * STAGEB_T, tid);
        }
        if (++stage >= NSTAGE) stage = 0;
    }
    // drain: wait for the final chunk's commit (in-order queue => all done)
    t_mbar_wait(ctrl + 8 + 8 * (uint32_t)((NC - 1) & 1),
                (uint32_t)(((NC - 1) >> 1) & 1));
    t_fence_after();

    // epilogue: warp w -> TMEM subpartition (w&3) rows, column block (w>>2)*32
    {
        int sub = warp & 3;
        int cbk = (warp >> 2) * 32;
        uint32_t r[32];
        t_ld_x32(r, tmem + cbk);
        t_wait_ld();
        int m = bm + sub * 32 + l;
        size_t rowbase = (size_t)m * Nn + bn + cbk;
        if (EPI == 0) {
            #pragma unroll
            for (int j = 0; j < 8; j++) {
                float4 s = {__uint_as_float(r[4*j])   + sbias[cbk + 4*j],
                            __uint_as_float(r[4*j+1]) + sbias[cbk + 4*j+1],
                            __uint_as_float(r[4*j+2]) + sbias[cbk + 4*j+2],
                            __uint_as_float(r[4*j+3]) + sbias[cbk + 4*j+3]};
                ((float4*)(C + rowbase))[j] = s;
            }
        } else if (EPI == 2) {
            #pragma unroll
            for (int j = 0; j < 8; j++) {
                float4 old = ((float4*)(C + rowbase))[j];
                float4 s = {__uint_as_float(r[4*j])   + sbias[cbk + 4*j]   + old.x,
                            __uint_as_float(r[4*j+1]) + sbias[cbk + 4*j+1] + old.y,
                            __uint_as_float(r[4*j+2]) + sbias[cbk + 4*j+2] + old.z,
                            __uint_as_float(r[4*j+3]) + sbias[cbk + 4*j+3] + old.w};
                ((float4*)(C + rowbase))[j] = s;
            }
        } else {  // EPI 1: relu -> fp16 hi/lo split
            #pragma unroll
            for (int j = 0; j < 16; j++) {
                float v0 = fmaxf(__uint_as_float(r[2*j])   + sbias[cbk + 2*j],   0.0f);
                float v1 = fmaxf(__uint_as_float(r[2*j+1]) + sbias[cbk + 2*j+1], 0.0f);
                __half h0 = __float2half_rn(v0);
                __half h1 = __float2half_rn(v1);
                __half2 h2 = __halves2half2(h0, h1);
                __half2 l2 = __halves2half2(
                    __float2half_rn(v0 - __half2float(h0)),
                    __float2half_rn(v1 - __half2float(h1)));
                *(__half2*)(Oh + rowbase + 2*j) = h2;
                *(__half2*)(Ol + rowbase + 2*j) = l2;
            }
        }
    }
    t_fence_before();
    __syncthreads();
    if (tid == 0) { t_mbar_inval(ctrl + 8); t_mbar_inval(ctrl + 16); }
    if (warp == 0) t_dealloc(tmem, 128);

#else
    // ===================== HMMA fallback (R12-exact) =====================
    uint32_t sb = smem_u32(smem);
    int wm = warp >> 2, wn = warp & 3;       // 4x4 warps, warp tile 32x32

    float acc[2][4][4];
    uint32_t cor[2][4][2];
    #pragma unroll
    for (int i = 0; i < 2; i++)
        #pragma unroll
        for (int j = 0; j < 4; j++) {
            #pragma unroll
            for (int k = 0; k < 4; k++) acc[i][j][k] = 0.0f;
            cor[i][j][0] = 0u; cor[i][j][1] = 0u;
        }

    int arow  = wm * 32 + (l & 15);
    int acolb = (l >> 4) * 16;
    int brow  = wn * 32 + ((l >> 4) & 1) * 8 + (l & 7);
    int bcolb = ((l >> 3) & 1) * 16;

    gemm_issue_chunk(pAh, pAl, pWh, pWl, K, 0, sb, tid);
    gemm_issue_chunk(pAh, pAl, pWh, pWl, K, 1, sb + STAGEB, tid);

    int stage = 0;
    for (int c = 0; c < NC; c++) {
        if (c + 1 < NC) cp_wait<1>(); else cp_wait<0>();
        __syncthreads();

        uint32_t sA  = sb + stage * STAGEB;
        uint32_t sAl = sA + TILEB;
        uint32_t sW  = sA + 2 * TILEB;
        uint32_t sWl = sA + 3 * TILEB;

        #pragma unroll
        for (int ks = 0; ks < KC / 16; ks++) {
            uint32_t ah[2][4], al4[2][4], wh[2][4], wl4[2][4];
            #pragma unroll
            for (int i = 0; i < 2; i++) {
                uint32_t off = (uint32_t)(arow + i * 16) * ARB + ks * 32 + acolb;
                ldsm_x4(ah[i],  sA  + off);
                ldsm_x4(al4[i], sAl + off);
            }
            #pragma unroll
            for (int jp = 0; jp < 2; jp++) {
                uint32_t off = (uint32_t)(brow + jp * 16) * ARB + ks * 32 + bcolb;
                ldsm_x4(wh[jp],  sW  + off);
                ldsm_x4(wl4[jp], sWl + off);
            }
            #pragma unroll
            for (int i = 0; i < 2; i++)
                #pragma unroll
                for (int j = 0; j < 4; j++) {
                    const uint32_t* bh = &wh[j >> 1][(j & 1) * 2];
                    const uint32_t* bl = &wl4[j >> 1][(j & 1) * 2];
                    mma_f32acc(acc[i][j], ah[i], bh);
                    mma_f16acc(cor[i][j], ah[i], bl);
                    mma_f16acc(cor[i][j], al4[i], bh);
                }
        }

        if (c + 2 < NC) {
            int ns = stage + 2; if (ns >= NSTAGE) ns -= NSTAGE;
            gemm_issue_chunk(pAh, pAl, pWh, pWl, K, c + 2, sb + ns * STAGEB, tid);
        }
        if (++stage >= NSTAGE) stage = 0;
    }

    int r0 = bm + wm * 32 + (l >> 2);
    int cb = wn * 32 + 2 * (l & 3);
    #pragma unroll
    for (int i = 0; i < 2; i++) {
        #pragma unroll
        for (int j = 0; j < 4; j++) {
            int col = cb + j * 8;
            float b0 = sbias[col], b1 = sbias[col + 1];
            #pragma unroll
            for (int half = 0; half < 2; half++) {
                __half2 ch = *(__half2*)&cor[i][j][half];
                float2 cf = __half22float2(ch);
                int m = r0 + i * 16 + half * 8;
                float v0 = acc[i][j][2 * half]     + cf.x + b0;
                float v1 = acc[i][j][2 * half + 1] + cf.y + b1;
                size_t idx = (size_t)m * Nn + bn + col;
                if (EPI == 0) {
                    float2 s = {v0, v1};
                    *(float2*)(C + idx) = s;
                } else if (EPI == 2) {
                    float2 old = *(const float2*)(C + idx);
                    float2 s = {v0 + old.x, v1 + old.y};
                    *(float2*)(C + idx) = s;
                } else {
                    v0 = fmaxf(v0, 0.0f);
                    v1 = fmaxf(v1, 0.0f);
                    __half h0 = __float2half_rn(v0);
                    __half h1 = __float2half_rn(v1);
                    __half2 h2 = __halves2half2(h0, h1);
                    __half2 l2 = __halves2half2(
                        __float2half_rn(v0 - __half2float(h0)),
                        __float2half_rn(v1 - __half2float(h1)));
                    *(__half2*)(Oh + idx) = h2;
                    *(__half2*)(Ol + idx) = l2;
                }
            }
        }
    }
#endif
}

// ---------------------------------------------------------------------------
// Fused attention: one CTA per (b,h), 512 threads, K/V resident in SMEM.
// ---------------------------------------------------------------------------
#define KST 68
#define ATTN_SMEM ((SEQ*KST + SEQ*HD + 16*4*SEQ) * 4)

__global__ __launch_bounds__(512, 1) void attn_kernel(const float* __restrict__ qkv,
                                                      const float* __restrict__ mask,
                                                      __half* __restrict__ oh,
                                                      __half* __restrict__ ol) {
    extern __shared__ __align__(16) float sm[];
    float* Ks = sm;
    float* Vs = Ks + SEQ * KST;
    float* Ps = Vs + SEQ * HD;

    int bh = blockIdx.x;
    int b  = bh >> 4;
    int h  = bh & 15;
    int tid = threadIdx.x;

    for (int idx = tid; idx < SEQ * 16; idx += 512) {
        int s = idx >> 4;
        int c = (idx & 15) << 2;
        size_t base = ((size_t)s * BATCH + b) * (3 * PD) + (size_t)h * HD + c;
        float4 k4 = *(const float4*)(qkv + base + PD);
        float4 v4 = *(const float4*)(qkv + base + 2 * PD);
        *(float4*)(Ks + s * KST + c) = k4;
        *(float4*)(Vs + s * HD + c) = v4;
    }
    __syncthreads();

    int warp = tid >> 5, lane = tid & 31;
    float* Pw = Ps + warp * 4 * SEQ;
    const size_t qtstep = (size_t)BATCH * 3 * PD;

    for (int it = 0; it < 4; it++) {
        int t0 = warp * 16 + it * 4;
        const float* qp0 = qkv + ((size_t)t0 * BATCH + b) * (3 * PD) + (size_t)h * HD;

        unsigned long long sc2[4][8];
        #pragma unroll
        for (int q = 0; q < 4; q++)
            #pragma unroll
            for (int j = 0; j < 8; j++) sc2[q][j] = 0ull;

        #pragma unroll 2
        for (int d4 = 0; d4 < 16; d4++) {
            const float* qb = qp0 + 4 * d4;
            ulonglong2 aq0 = *(const ulonglong2*)(qb);
            ulonglong2 aq1 = *(const ulonglong2*)(qb + qtstep);
            ulonglong2 aq2 = *(const ulonglong2*)(qb + 2 * qtstep);
            ulonglong2 aq3 = *(const ulonglong2*)(qb + 3 * qtstep);
            #pragma unroll
            for (int j = 0; j < 8; j++) {
                int s = lane + 32 * j;
                ulonglong2 k2 = *(const ulonglong2*)(Ks + s * KST + 4 * d4);
                sc2[0][j] = fma2(aq0.x, k2.x, sc2[0][j]);
                sc2[0][j] = fma2(aq0.y, k2.y, sc2[0][j]);
                sc2[1][j] = fma2(aq1.x, k2.x, sc2[1][j]);
                sc2[1][j] = fma2(aq1.y, k2.y, sc2[1][j]);
                sc2[2][j] = fma2(aq2.x, k2.x, sc2[2][j]);
                sc2[2][j] = fma2(aq2.y, k2.y, sc2[2][j]);
                sc2[3][j] = fma2(aq3.x, k2.x, sc2[3][j]);
                sc2[3][j] = fma2(aq3.y, k2.y, sc2[3][j]);
            }
        }

        #pragma unroll
        for (int q = 0; q < 4; q++) {
            float pr[8];
            const float* mrow = mask + (size_t)(t0 + q) * SEQ;
            #pragma unroll
            for (int j = 0; j < 8; j++) {
                float lo, hi;
                unpack2(sc2[q][j], lo, hi);
                pr[j] = (lo + hi) * 0.125f + mrow[lane + 32 * j];
            }
            float mx = pr[0];
            #pragma unroll
            for (int j = 1; j < 8; j++) mx = fmaxf(mx, pr[j]);
            #pragma unroll
            for (int o = 16; o; o >>= 1) mx = fmaxf(mx, __shfl_xor_sync(0xffffffffu, mx, o));
            float sum = 0.0f;
            #pragma unroll
            for (int j = 0; j < 8; j++) { pr[j] = __expf(pr[j] - mx); sum += pr[j]; }
            #pragma unroll
            for (int o = 16; o; o >>= 1) sum += __shfl_xor_sync(0xffffffffu, sum, o);
            float inv = 1.0f / sum;
            #pragma unroll
            for (int j = 0; j < 8; j++) Pw[q * SEQ + lane + 32 * j] = pr[j] * inv;
        }
        __syncwarp();

        float2 acc0 = {0, 0}, acc1 = {0, 0}, acc2v = {0, 0}, acc3 = {0, 0};
        const float* vcol = Vs + 2 * lane;
        for (int s = 0; s < SEQ; s++) {
            float2 v2 = *(const float2*)(vcol + s * HD);
            float p0 = Pw[s];
            float p1 = Pw[SEQ + s];
            float p2 = Pw[2 * SEQ + s];
            float p3 = Pw[3 * SEQ + s];
            acc0.x = fmaf(p0, v2.x, acc0.x); acc0.y = fmaf(p0, v2.y, acc0.y);
            acc1.x = fmaf(p1, v2.x, acc1.x); acc1.y = fmaf(p1, v2.y, acc1.y);
            acc2v.x = fmaf(p2, v2.x, acc2v.x); acc2v.y = fmaf(p2, v2.y, acc2v.y);
            acc3.x = fmaf(p3, v2.x, acc3.x); acc3.y = fmaf(p3, v2.y, acc3.y);
        }
        size_t obase = ((size_t)t0 * BATCH + b) * PD + (size_t)h * HD + 2 * lane;
        size_t ostep = (size_t)BATCH * PD;
        float2 accs[4] = {acc0, acc1, acc2v, acc3};
        #pragma unroll
        for (int q = 0; q < 4; q++) {
            size_t oidx = obase + q * ostep;
            __half hx = __float2half_rn(accs[q].x);
            __half hy = __float2half_rn(accs[q].y);
            __half2 h2 = __halves2half2(hx, hy);
            __half2 l2 = __halves2half2(
                __float2half_rn(accs[q].x - __half2float(hx)),
                __float2half_rn(accs[q].y - __half2float(hy)));
            *(__half2*)(oh + oidx) = h2;
            *(__half2*)(ol + oidx) = l2;
        }
        __syncwarp();
    }
}

// ---------------------------------------------------------------------------
// Host orchestration
// ---------------------------------------------------------------------------
extern "C" void kernel_launch(void* const* d_in, const int* in_sizes, int n_in,
                              void* d_out, int out_size) {
    const float* src  = (const float*)d_in[0];
    const float* mask = (const float*)d_in[1];
    const float* Wqkv = (const float*)d_in[2];
    const float* bqkv = (const float*)d_in[3];
    const float* Wo   = (const float*)d_in[4];
    const float* bo   = (const float*)d_in[5];
    const float* ln1g = (const float*)d_in[6];
    const float* ln1b = (const float*)d_in[7];
    const float* ln2g = (const float*)d_in[8];
    const float* ln2b = (const float*)d_in[9];
    const float* W1   = (const float*)d_in[10];
    const float* b1   = (const float*)d_in[11];
    const float* W2   = (const float*)d_in[12];
    const float* b2   = (const float*)d_in[13];
    const float* lnfg = (const float*)d_in[14];
    const float* lnfb = (const float*)d_in[15];

    float* x = (float*)d_out;

    void *pqkv, *pah, *pal, *pffh, *pffl, *pwh, *pwl;
    cudaGetSymbolAddress(&pqkv, g_qkv);
    cudaGetSymbolAddress(&pah, g_ah);
    cudaGetSymbolAddress(&pal, g_al);
    cudaGetSymbolAddress(&pffh, g_ffh);
    cudaGetSymbolAddress(&pffl, g_ffl);
    cudaGetSymbolAddress(&pwh, g_wh);
    cudaGetSymbolAddress(&pwl, g_wl);
    float* qk = (float*)pqkv;
    __half* ah  = (__half*)pah;
    __half* al  = (__half*)pal;
    __half* ffh = (__half*)pffh;
    __half* ffl = (__half*)pffl;
    __half* wh  = (__half*)pwh;
    __half* wl  = (__half*)pwl;

    cudaFuncSetAttribute(attn_kernel, cudaFuncAttributeMaxDynamicSharedMemorySize,
                         ATTN_SMEM);
    cudaFuncSetAttribute(tc_gemm<0>, cudaFuncAttributeMaxDynamicSharedMemorySize,
                         GEMM_SMEM);
    cudaFuncSetAttribute(tc_gemm<1>, cudaFuncAttributeMaxDynamicSharedMemorySize,
                         GEMM_SMEM);
    cudaFuncSetAttribute(tc_gemm<2>, cudaFuncAttributeMaxDynamicSharedMemorySize,
                         GEMM_SMEM);

    // x = src
    copy_kernel<<<ROWS * NF / (256 * 4), 256>>>(src, x);

    dim3 gQKV(3 * PD / 128, ROWS / 128);   // (24, 64)
    dim3 gWO(NF / 128, ROWS / 128);        // (8, 64)
    dim3 gW1(FF / 128, ROWS / 128);        // (32, 64)
    dim3 gW2(NF / 128, ROWS / 128);        // (8, 64)

    for (int l = 0; l < LAYERS; l++) {
        const float* wqkv = Wqkv + (size_t)l * 3 * PD * NF;
        const float* bq   = bqkv + (size_t)l * 3 * PD;
        const float* wo   = Wo   + (size_t)l * NF * PD;
        const float* bo_  = bo   + (size_t)l * NF;
        const float* w1   = W1   + (size_t)l * FF * NF;
        const float* bb1  = b1   + (size_t)l * FF;
        const float* w2   = W2   + (size_t)l * NF * FF;
        const float* bb2  = b2   + (size_t)l * NF;

        // --- attention block ---
        ln_kernel<1><<<ROWS, 256>>>(x, ln1g + (size_t)l * NF, ln1b + (size_t)l * NF,
                                    nullptr, ah, al);
        convw_kernel<<<(3 * PD * NF) / 1024, 256>>>(wqkv, wh, wl);
        tc_gemm<0><<<gQKV, 512, GEMM_SMEM>>>(ah, al, wh, wl, bq, qk,
                                             nullptr, nullptr, 3 * PD, NF);
        attn_kernel<<<BATCH * NH, 512, ATTN_SMEM>>>(qk, mask, ah, al);
        convw_kernel<<<(NF * PD) / 1024, 256>>>(wo, wh, wl);
        tc_gemm<2><<<gWO, 512, GEMM_SMEM>>>(ah, al, wh, wl, bo_, x,
                                            nullptr, nullptr, NF, PD);

        // --- FFN block ---
        ln_kernel<1><<<ROWS, 256>>>(x, ln2g + (size_t)l * NF, ln2b + (size_t)l * NF,
                                    nullptr, ah, al);
        convw_kernel<<<(FF * NF) / 1024, 256>>>(w1, wh, wl);
        tc_gemm<1><<<gW1, 512, GEMM_SMEM>>>(ah, al, wh, wl, bb1, nullptr,
                                            ffh, ffl, FF, NF);
        convw_kernel<<<(NF * FF) / 1024, 256>>>(w2, wh, wl);
        tc_gemm<2><<<gW2, 512, GEMM_SMEM>>>(ffh, ffl, wh, wl, bb2, x,
                                            nullptr, nullptr, NF, FF);
    }

    // final LN (fp32, in-place on d_out)
    ln_kernel<0><<<ROWS, 256>>>(x, lnfg, lnfb, x, nullptr, nullptr);
}